// round 14
// baseline (speedup 1.0000x reference)
#include <cuda_runtime.h>
#include <cuda_bf16.h>
#include <math.h>
#include <stdint.h>

#define LEAKK 0.01f
#define EPSS  1e-5f

typedef __nv_bfloat16 bf16;

// packed fp32x2 FMA — enc0 kernel only
#define FMA2(acc, a, b) \
    asm("fma.rn.f32x2 %0, %1, %2, %0;" : "+l"(acc) : "l"(a), "l"(b))

__device__ __forceinline__ float2 unpk(unsigned long long p) {
    unsigned int lo, hi;
    asm("mov.b64 {%0,%1}, %2;" : "=r"(lo), "=r"(hi) : "l"(p));
    return make_float2(__uint_as_float(lo), __uint_as_float(hi));
}

// mma.sync m16n8k16 row.col bf16 -> f32
__device__ __forceinline__ void mma16816(float* d, const uint32_t* a,
                                         uint32_t b0, uint32_t b1) {
    asm volatile(
        "mma.sync.aligned.m16n8k16.row.col.f32.bf16.bf16.f32 "
        "{%0,%1,%2,%3}, {%4,%5,%6,%7}, {%8,%9}, {%0,%1,%2,%3};"
        : "+f"(d[0]), "+f"(d[1]), "+f"(d[2]), "+f"(d[3])
        : "r"(a[0]), "r"(a[1]), "r"(a[2]), "r"(a[3]), "r"(b0), "r"(b1));
}

// ---------------- scratch (device globals; no allocation) ----------------
__device__ float g_y0[16*64*64*64];
__device__ float g_y1[16*128*32*32];
__device__ float g_y2[16*256*16*16];
__device__ float g_z [16*256*8*8];
__device__ float g_q [16*256*8*8];
__device__ float g_d0[16*128*32*32];
__device__ float g_d1[16*64*64*64];
__device__ float g_d2[16*32*128*128];
__device__ float g_wt[4096];
__device__ float g_part[4194304];
__device__ bf16  g_wbh[2269184];
__device__ bf16  g_wbl[2269184];
__device__ float g_scale[6*256];
__device__ float g_shift[6*256];
__device__ float g_cnorm[512];
__device__ float g_rowloss[1024];
__device__ float2 g_bnp[256*8];

// ---------------- smem-tiled transpose (enc0 weights) ---------------------
__global__ void wtrans(const float* __restrict__ in, float* __restrict__ outp,
                       int R, int Ccol) {
    __shared__ float t[32][33];
    int bx = blockIdx.x * 32, by = blockIdx.y * 32;
    int tx = threadIdx.x, ty = threadIdx.y;
#pragma unroll
    for (int j = 0; j < 4; j++) {
        int xx = bx + tx, yy = by + ty + j * 8;
        if (xx < Ccol && yy < R) t[ty + j * 8][tx] = in[yy * Ccol + xx];
    }
    __syncthreads();
#pragma unroll
    for (int j = 0; j < 4; j++) {
        int xx = by + tx, yy = bx + ty + j * 8;
        if (xx < R && yy < Ccol) outp[yy * R + xx] = t[tx][ty + j * 8];
    }
}

// ---------------- weight split: fp32 -> bf16 hi/lo -------------------------
__global__ void wsplit(const float* __restrict__ w, bf16* __restrict__ h,
                       bf16* __restrict__ l, int n) {
    int i = blockIdx.x * blockDim.x + threadIdx.x;
    if (i >= n) return;
    float v = w[i];
    bf16 hh = __float2bfloat16(v);
    h[i] = hh;
    l[i] = __float2bfloat16(v - __bfloat162float(hh));
}

// ---------------- transpose + split: in[R][C] -> h/l [C][R] ----------------
__global__ void wsplit_t(const float* __restrict__ in, bf16* __restrict__ oh,
                         bf16* __restrict__ ol, int R, int C) {
    __shared__ float t[32][33];
    int bx = blockIdx.x * 32, by = blockIdx.y * 32;
    int tx = threadIdx.x, ty = threadIdx.y;
#pragma unroll
    for (int j = 0; j < 4; j++) {
        int xx = bx + tx, yy = by + ty + j * 8;
        if (xx < C && yy < R) t[ty + j * 8][tx] = in[yy * C + xx];
    }
    __syncthreads();
#pragma unroll
    for (int j = 0; j < 4; j++) {
        int cc = bx + ty + j * 8, rr = by + tx;
        if (cc < C && rr < R) {
            float v = t[tx][ty + j * 8];
            bf16 hh = __float2bfloat16(v);
            oh[cc * R + rr] = hh;
            ol[cc * R + rr] = __float2bfloat16(v - __bfloat162float(hh));
        }
    }
}

// ---------------- enc0 conv (FMA2 64x64 tile, proven) ----------------------
template<int CIN, int COUT, int H, int W>
__global__ void __launch_bounds__(256)
gconv(const float* __restrict__ x, const float* __restrict__ wt,
      const float* __restrict__ bias, float* __restrict__ out) {
    constexpr int Ho = H / 2, Wo = W / 2, HoWo = Ho * Wo;
    __shared__ float Asd[2][16][128];
    __shared__ float Bs [2][16][64];
    const int tid = threadIdx.x;
    const int tx = tid & 15, ty = tid >> 4;
    const int p0 = blockIdx.x * 64, co0 = blockIdx.y * 64;
    const int pp = tid & 63, cc = tid & 63;
    int kkj[4], boff[4]; bool val[4];
    {
        int gp = p0 + pp;
        int b = gp / HoWo, r = gp % HoWo;
        int oh = r / Wo, ow = r % Wo;
#pragma unroll
        for (int j = 0; j < 4; j++) {
            int kk = (tid >> 6) + 4 * j;
            int kh = kk >> 2, kw = kk & 3;
            int ih = 2 * oh - 1 + kh, iw = 2 * ow - 1 + kw;
            val[j] = (ih >= 0) && (ih < H) && (iw >= 0) && (iw < W);
            kkj[j] = kk;
            boff[j] = (b * CIN) * H * W + ih * W + iw;
        }
    }
    float bv[4], av[4];
    auto gather = [&](int ci) {
#pragma unroll
        for (int j = 0; j < 4; j++) {
            float v = 0.f;
            if (val[j]) v = x[boff[j] + ci * (H * W)];
            bv[j] = v;
            av[j] = wt[(ci * 16 + kkj[j]) * COUT + co0 + cc];
        }
    };
    auto stobuf = [&](int nb) {
#pragma unroll
        for (int j = 0; j < 4; j++) {
            Bs[nb][kkj[j]][pp] = bv[j];
            *(float2*)&Asd[nb][kkj[j]][2 * cc] = make_float2(av[j], av[j]);
        }
    };
    gather(0); stobuf(0);
    __syncthreads();
    unsigned long long acc[4][2];
#pragma unroll
    for (int i = 0; i < 4; i++) { acc[i][0] = 0ULL; acc[i][1] = 0ULL; }
    for (int c = 0; c < CIN; c++) {
        int cur = c & 1;
        bool more = (c + 1) < CIN;
        if (more) gather(c + 1);
#pragma unroll
        for (int k = 0; k < 16; k++) {
            ulonglong2 b2  = *(const ulonglong2*)&Bs [cur][k][4 * tx];
            ulonglong2 a01 = *(const ulonglong2*)&Asd[cur][k][8 * ty];
            ulonglong2 a23 = *(const ulonglong2*)&Asd[cur][k][8 * ty + 4];
            FMA2(acc[0][0], a01.x, b2.x); FMA2(acc[0][1], a01.x, b2.y);
            FMA2(acc[1][0], a01.y, b2.x); FMA2(acc[1][1], a01.y, b2.y);
            FMA2(acc[2][0], a23.x, b2.x); FMA2(acc[2][1], a23.x, b2.y);
            FMA2(acc[3][0], a23.y, b2.x); FMA2(acc[3][1], a23.y, b2.y);
        }
        if (more) stobuf(cur ^ 1);
        __syncthreads();
    }
    const int b = p0 / HoWo;
    const int rb = (p0 % HoWo) + 4 * tx;
#pragma unroll
    for (int i = 0; i < 4; i++) {
        int co = co0 + 4 * ty + i;
        float bvs = bias[co];
        float2 u0 = unpk(acc[i][0]);
        float2 u1 = unpk(acc[i][1]);
        *(float4*)&out[(b * COUT + co) * HoWo + rb]
            = make_float4(u0.x + bvs, u0.y + bvs, u1.x + bvs, u1.y + bvs);
    }
}

// ---------------- HMMA conv GEMM: 128px x 128co, K32 chunks ----------------
template<int CIN, int COUT, int H, int W, bool BN, int NSPLIT>
__global__ void __launch_bounds__(256)
tconv(const float* __restrict__ x, const bf16* __restrict__ wh,
      const bf16* __restrict__ wl,
      const float* __restrict__ scale, const float* __restrict__ shift,
      float* __restrict__ out) {
    constexpr int Ho = H / 2, Wo = W / 2, HoWo = Ho * Wo;
    constexpr int Kfull = CIN * 16;
    constexpr int Kslice = Kfull / NSPLIT;
    constexpr int NCH = Kslice / 32;
    constexpr long SLICE = (long)16 * HoWo * COUT;

    // [row][32] bf16 per array = 8KB each
    __shared__ __align__(16) bf16 AsH[4096], AsL[4096], BsH[4096], BsL[4096];
    const uint32_t* AH32 = (const uint32_t*)AsH;
    const uint32_t* AL32 = (const uint32_t*)AsL;
    const uint32_t* BH32 = (const uint32_t*)BsH;
    const uint32_t* BL32 = (const uint32_t*)BsL;

    const int tid = threadIdx.x;
    const int warp = tid >> 5, lane = tid & 31;
    const int g = lane >> 2, tg = lane & 3;
    const int m0 = warp * 16;

    const int p0 = blockIdx.x * 128;
    const int n0 = blockIdx.y * 128;
    const int k0 = blockIdx.z * Kslice;
    const int pb = tid & 127, half = tid >> 7;   // half selects 16-k subrange

    // A-gather precompute: all 16 kk positions of this pixel
    int boffs[16]; unsigned vm = 0;
    {
        int gp = p0 + pb;
        int b = gp / HoWo, r = gp % HoWo;
        int oh = r / Wo, ow = r % Wo;
        int ih0 = 2 * oh - 1, iw0 = 2 * ow - 1;
        int xbase = b * CIN * H * W;
#pragma unroll
        for (int j = 0; j < 16; j++) {
            int kh = j >> 2, kw = j & 3;
            int ih = ih0 + kh, iw = iw0 + kw;
            if (ih >= 0 && ih < H && iw >= 0 && iw < W) vm |= (1u << j);
            boffs[j] = xbase + ih * W + iw;
        }
    }

    float acc[16][4];
#pragma unroll
    for (int nt = 0; nt < 16; nt++)
#pragma unroll
        for (int i = 0; i < 4; i++) acc[nt][i] = 0.f;

    for (int c = 0; c < NCH; c++) {
        // ---- fill A: this thread covers one ci (16 kk) at k-sub 'half' ----
        {
            int ci = (k0 + c * 32 + half * 16) >> 4;
            float sc_ = 1.f, sf_ = 0.f;
            if (BN) { sc_ = scale[ci]; sf_ = shift[ci]; }
            const float* xch = x + (long)ci * (H * W);
#pragma unroll
            for (int q8 = 0; q8 < 2; q8++) {
                uint4 uh, ul;
                bf16* hp = (bf16*)&uh; bf16* lp = (bf16*)&ul;
#pragma unroll
                for (int e = 0; e < 8; e++) {
                    int j = q8 * 8 + e;
                    float v = 0.f;
                    if ((vm >> j) & 1) {
                        v = xch[boffs[j]];
                        if (BN) { v = v * sc_ + sf_; v = fmaxf(v, LEAKK * v); }
                    }
                    bf16 hh = __float2bfloat16(v);
                    hp[e] = hh;
                    lp[e] = __float2bfloat16(v - __bfloat162float(hh));
                }
                int off = pb * 32 + half * 16 + q8 * 8;
                *(uint4*)&AsH[off] = uh;
                *(uint4*)&AsL[off] = ul;
            }
        }
        // ---- fill B ----
        {
            long roff = (long)(n0 + pb) * Kfull + k0 + c * 32 + half * 16;
            int off = pb * 32 + half * 16;
            *(uint4*)&BsH[off]     = *(const uint4*)(wh + roff);
            *(uint4*)&BsH[off + 8] = *(const uint4*)(wh + roff + 8);
            *(uint4*)&BsL[off]     = *(const uint4*)(wl + roff);
            *(uint4*)&BsL[off + 8] = *(const uint4*)(wl + roff + 8);
        }
        __syncthreads();
        // ---- 2 k-subchunks of MMA ----
#pragma unroll
        for (int s = 0; s < 2; s++) {
            uint32_t ah[4], al[4];
            int ar0 = (m0 + g) * 16 + s * 8, ar1 = (m0 + g + 8) * 16 + s * 8;
            ah[0] = AH32[ar0 + tg];     ah[1] = AH32[ar1 + tg];
            ah[2] = AH32[ar0 + tg + 4]; ah[3] = AH32[ar1 + tg + 4];
            al[0] = AL32[ar0 + tg];     al[1] = AL32[ar1 + tg];
            al[2] = AL32[ar0 + tg + 4]; al[3] = AL32[ar1 + tg + 4];
#pragma unroll
            for (int nt = 0; nt < 16; nt++) {
                int nr = (nt * 8 + g) * 16 + s * 8;
                uint32_t bh0 = BH32[nr + tg], bh1 = BH32[nr + tg + 4];
                uint32_t bl0 = BL32[nr + tg], bl1 = BL32[nr + tg + 4];
                mma16816(acc[nt], ah, bh0, bh1);
                mma16816(acc[nt], ah, bl0, bl1);
                mma16816(acc[nt], al, bh0, bh1);
            }
        }
        __syncthreads();
    }

    // ---- epilogue ----
    float* po = out + (NSPLIT > 1 ? (long)blockIdx.z * SLICE : 0);
    const int r0 = p0 + m0 + g, r1 = r0 + 8;
    const int b0_ = r0 / HoWo, ri0 = r0 % HoWo;
    const int b1_ = r1 / HoWo, ri1 = r1 % HoWo;
#pragma unroll
    for (int nt = 0; nt < 16; nt++) {
        int co = n0 + nt * 8 + 2 * tg;
        po[((long)(b0_ * COUT + co)) * HoWo + ri0]     = acc[nt][0];
        po[((long)(b0_ * COUT + co + 1)) * HoWo + ri0] = acc[nt][1];
        po[((long)(b1_ * COUT + co)) * HoWo + ri1]     = acc[nt][2];
        po[((long)(b1_ * COUT + co + 1)) * HoWo + ri1] = acc[nt][3];
    }
}

// ---------------- HMMA convt GEMM: 128px x 128m, K32 chunks -----------------
template<int CIN, int COUT, int KS, int H, int W, bool BN, int NSPLIT>
__global__ void __launch_bounds__(256)
tconvt(const float* __restrict__ x, const bf16* __restrict__ wh,
       const bf16* __restrict__ wl,
       const float* __restrict__ scale, const float* __restrict__ shift,
       float* __restrict__ out) {
    constexpr int HW = H * W;
    constexpr int KK = KS * KS;
    constexpr int Hout = H * KS, Wout = W * KS;
    constexpr int Kslice = CIN / NSPLIT;
    constexpr int NCH = Kslice / 32;
    constexpr long SLICE = (long)16 * COUT * Hout * Wout;

    __shared__ __align__(16) bf16 AsH[4096], AsL[4096], BsH[4096], BsL[4096];
    const uint32_t* AH32 = (const uint32_t*)AsH;
    const uint32_t* AL32 = (const uint32_t*)AsL;
    const uint32_t* BH32 = (const uint32_t*)BsH;
    const uint32_t* BL32 = (const uint32_t*)BsL;

    const int tid = threadIdx.x;
    const int warp = tid >> 5, lane = tid & 31;
    const int g = lane >> 2, tg = lane & 3;
    const int m0 = warp * 16;

    const int p0 = blockIdx.x * 128;
    const int n0 = blockIdx.y * 128;
    const int cbase = blockIdx.z * Kslice;
    const int pb = tid & 127, half = tid >> 7;

    const int gp = p0 + pb;
    const int bI0 = gp / HW, rI0 = gp % HW;
    const long xrow = (long)bI0 * CIN * HW + rI0;

    float acc[16][4];
#pragma unroll
    for (int nt = 0; nt < 16; nt++)
#pragma unroll
        for (int i = 0; i < 4; i++) acc[nt][i] = 0.f;

    for (int c = 0; c < NCH; c++) {
        {
            int cs = cbase + c * 32 + half * 16;
#pragma unroll
            for (int q8 = 0; q8 < 2; q8++) {
                uint4 uh, ul;
                bf16* hp = (bf16*)&uh; bf16* lp = (bf16*)&ul;
#pragma unroll
                for (int e = 0; e < 8; e++) {
                    int ci = cs + q8 * 8 + e;
                    float v = x[xrow + (long)ci * HW];
                    if (BN) {
                        float t = v * scale[ci] + shift[ci];
                        v = fmaxf(t, LEAKK * t);
                    }
                    bf16 hh = __float2bfloat16(v);
                    hp[e] = hh;
                    lp[e] = __float2bfloat16(v - __bfloat162float(hh));
                }
                int off = pb * 32 + half * 16 + q8 * 8;
                *(uint4*)&AsH[off] = uh;
                *(uint4*)&AsL[off] = ul;
            }
        }
        {
            long roff = (long)(n0 + pb) * CIN + cbase + c * 32 + half * 16;
            int off = pb * 32 + half * 16;
            *(uint4*)&BsH[off]     = *(const uint4*)(wh + roff);
            *(uint4*)&BsH[off + 8] = *(const uint4*)(wh + roff + 8);
            *(uint4*)&BsL[off]     = *(const uint4*)(wl + roff);
            *(uint4*)&BsL[off + 8] = *(const uint4*)(wl + roff + 8);
        }
        __syncthreads();
#pragma unroll
        for (int s = 0; s < 2; s++) {
            uint32_t ah[4], al[4];
            int ar0 = (m0 + g) * 16 + s * 8, ar1 = (m0 + g + 8) * 16 + s * 8;
            ah[0] = AH32[ar0 + tg];     ah[1] = AH32[ar1 + tg];
            ah[2] = AH32[ar0 + tg + 4]; ah[3] = AH32[ar1 + tg + 4];
            al[0] = AL32[ar0 + tg];     al[1] = AL32[ar1 + tg];
            al[2] = AL32[ar0 + tg + 4]; al[3] = AL32[ar1 + tg + 4];
#pragma unroll
            for (int nt = 0; nt < 16; nt++) {
                int nr = (nt * 8 + g) * 16 + s * 8;
                uint32_t bh0 = BH32[nr + tg], bh1 = BH32[nr + tg + 4];
                uint32_t bl0 = BL32[nr + tg], bl1 = BL32[nr + tg + 4];
                mma16816(acc[nt], ah, bh0, bh1);
                mma16816(acc[nt], ah, bl0, bl1);
                mma16816(acc[nt], al, bh0, bh1);
            }
        }
        __syncthreads();
    }

    float* po = out + (NSPLIT > 1 ? (long)blockIdx.z * SLICE : 0);
    const int r0 = p0 + m0 + g, r1 = r0 + 8;
    const int b0_ = r0 / HW, ri0 = r0 % HW;
    const int b1_ = r1 / HW, ri1 = r1 % HW;
    const int ih0 = ri0 / W, iw0 = ri0 % W;
    const int ih1 = ri1 / W, iw1 = ri1 % W;
#pragma unroll
    for (int nt = 0; nt < 16; nt++) {
        int n = n0 + nt * 8 + 2 * tg;
#pragma unroll
        for (int l = 0; l < 2; l++) {
            int nn = n + l;
            int co = nn / KK, rem = nn % KK;
            int ki = rem / KS, kj = rem % KS;
            po[((long)(b0_ * COUT + co) * Hout + ih0 * KS + ki) * Wout + iw0 * KS + kj]
                = acc[nt][l];
            po[((long)(b1_ * COUT + co) * Hout + ih1 * KS + ki) * Wout + iw1 * KS + kj]
                = acc[nt][2 + l];
        }
    }
}

// ---------------- K-split combine (nullable bias) ---------------------------
__global__ void combine(const float* __restrict__ part, const float* __restrict__ bias,
                        float* __restrict__ out, int len, int S, int HWo, int CO) {
    int i = blockIdx.x * blockDim.x + threadIdx.x;
    if (i >= len) return;
    float s = 0.f;
    for (int k = 0; k < S; k++) s += part[i + (long)k * len];
    float bv = bias ? bias[(i / HWo) % CO] : 0.f;
    out[i] = s + bv;
}

// ---------------- BN batch stats (two-phase) --------------------------------
__global__ void bnpart(const float* __restrict__ y, int C, int HW,
                       float2* __restrict__ part) {
    int c = blockIdx.x, s = blockIdx.y;
    int seg = HW / 8, r0 = s * seg;
    float sm = 0.f, s2 = 0.f;
    for (int b = 0; b < 16; b++) {
        const float* p = y + (long)(b * C + c) * HW;
        for (int r = r0 + threadIdx.x; r < r0 + seg; r += 256) {
            float v = p[r];
            sm += v; s2 += v * v;
        }
    }
    __shared__ float sh[256], sh2[256];
    sh[threadIdx.x] = sm; sh2[threadIdx.x] = s2;
    __syncthreads();
    for (int o = 128; o > 0; o >>= 1) {
        if (threadIdx.x < o) { sh[threadIdx.x] += sh[threadIdx.x + o];
                               sh2[threadIdx.x] += sh2[threadIdx.x + o]; }
        __syncthreads();
    }
    if (threadIdx.x == 0) part[c * 8 + s] = make_float2(sh[0], sh2[0]);
}

__global__ void bnfin(const float2* __restrict__ part,
                      const float* __restrict__ g, const float* __restrict__ bb,
                      float* __restrict__ scale, float* __restrict__ shift,
                      int C, float invn) {
    int c = threadIdx.x;
    if (c >= C) return;
    float sm = 0.f, s2 = 0.f;
#pragma unroll
    for (int s = 0; s < 8; s++) { float2 p = part[c * 8 + s]; sm += p.x; s2 += p.y; }
    float m = sm * invn;
    float v = s2 * invn - m * m;
    float sc = g[c] * rsqrtf(v + EPSS);
    scale[c] = sc;
    shift[c] = bb[c] - m * sc;
}

// ---------------- codebook squared norms ------------------------------------
__global__ void cnormk(const float* __restrict__ cb, float* __restrict__ cn) {
    int c = blockIdx.x;
    float v = cb[c * 256 + threadIdx.x];
    __shared__ float sh[256];
    sh[threadIdx.x] = v * v;
    __syncthreads();
    for (int o = 128; o > 0; o >>= 1) {
        if (threadIdx.x < o) sh[threadIdx.x] += sh[threadIdx.x + o];
        __syncthreads();
    }
    if (threadIdx.x == 0) cn[c] = sh[0];
}

// ---------------- vector quantizer ------------------------------------------
__global__ void vqk(const float* __restrict__ z, const float* __restrict__ cb,
                    const float* __restrict__ cn, float* __restrict__ q,
                    float* __restrict__ rowloss,
                    float* __restrict__ out_idx, float* __restrict__ out_mind) {
    int row = blockIdx.x;
    int b = row >> 6, hw = row & 63;
    int tid = threadIdx.x, lane = tid & 31, warp = tid >> 5;
    __shared__ float zf[256];
    __shared__ float red[256];

    zf[tid] = z[(b * 256 + tid) * 64 + hw];
    red[tid] = zf[tid] * zf[tid];
    __syncthreads();
    for (int o = 128; o > 0; o >>= 1) {
        if (tid < o) red[tid] += red[tid + o];
        __syncthreads();
    }
    float znorm = red[0];
    __syncthreads();

    float best = 3.4e38f; int bidx = 1 << 20;
    for (int code = warp; code < 512; code += 8) {
        const float* cr = cb + code * 256;
        float dot = 0.f;
#pragma unroll
        for (int k = 0; k < 8; k++) dot += cr[lane + 32 * k] * zf[lane + 32 * k];
#pragma unroll
        for (int o = 16; o > 0; o >>= 1) dot += __shfl_down_sync(0xffffffffu, dot, o);
        if (lane == 0) {
            float d2 = znorm - 2.f * dot + cn[code];
            if (d2 < best || (d2 == best && code < bidx)) { best = d2; bidx = code; }
        }
    }
    __shared__ float wbest[8]; __shared__ int widx[8];
    if (lane == 0) { wbest[warp] = best; widx[warp] = bidx; }
    __syncthreads();
    if (tid == 0) {
        float bb = wbest[0]; int bi = widx[0];
        for (int w = 1; w < 8; w++)
            if (wbest[w] < bb || (wbest[w] == bb && widx[w] < bi)) { bb = wbest[w]; bi = widx[w]; }
        wbest[0] = bb; widx[0] = bi;
    }
    __syncthreads();
    int idx = widx[0];
    float mind = wbest[0];

    float qv = cb[idx * 256 + tid];
    q[(b * 256 + tid) * 64 + hw] = qv;
    float diff = qv - zf[tid];
    red[tid] = diff * diff;
    __syncthreads();
    for (int o = 128; o > 0; o >>= 1) {
        if (tid < o) red[tid] += red[tid + o];
        __syncthreads();
    }
    if (tid == 0) {
        rowloss[row] = red[0];
        out_idx[row] = (float)idx;
        out_mind[row] = mind;
    }
}

__global__ void lossfin(const float* __restrict__ rowloss, float* __restrict__ out) {
    __shared__ float sh[256];
    float s = 0.f;
    for (int i = threadIdx.x; i < 1024; i += 256) s += rowloss[i];
    sh[threadIdx.x] = s; __syncthreads();
    for (int o = 128; o > 0; o >>= 1) {
        if (threadIdx.x < o) sh[threadIdx.x] += sh[threadIdx.x + o];
        __syncthreads();
    }
    if (threadIdx.x == 0) {
        float L = sh[0] / (1024.f * 256.f);
        out[786432] = L;
        out[786433] = L;
    }
}

// ---------------- final 1x1 conv + tanh -------------------------------------
__global__ void final1x1(const float* __restrict__ h, const float* __restrict__ w3,
                         const float* __restrict__ b3,
                         const float* __restrict__ scale, const float* __restrict__ shift,
                         float* __restrict__ out) {
    __shared__ float sw[96], ssc[32], ssh[32], sb[3];
    if (threadIdx.x < 96) sw[threadIdx.x] = w3[threadIdx.x];
    if (threadIdx.x < 32) { ssc[threadIdx.x] = scale[threadIdx.x];
                            ssh[threadIdx.x] = shift[threadIdx.x]; }
    if (threadIdx.x < 3) sb[threadIdx.x] = b3[threadIdx.x];
    __syncthreads();
    const int HW = 128 * 128;
    int gid = blockIdx.x * blockDim.x + threadIdx.x;
    int b = gid / HW, r = gid % HW;
    float a0 = 0.f, a1 = 0.f, a2 = 0.f;
#pragma unroll 8
    for (int c = 0; c < 32; c++) {
        float v = h[(b * 32 + c) * HW + r];
        v = v * ssc[c] + ssh[c];
        v = fmaxf(v, LEAKK * v);
        a0 += v * sw[c];
        a1 += v * sw[32 + c];
        a2 += v * sw[64 + c];
    }
    out[(b * 3 + 0) * HW + r] = tanhf(a0 + sb[0]);
    out[(b * 3 + 1) * HW + r] = tanhf(a1 + sb[1]);
    out[(b * 3 + 2) * HW + r] = tanhf(a2 + sb[2]);
}

// ----------------------------------------------------------------------------
extern "C" void kernel_launch(void* const* d_in, const int* in_sizes, int n_in,
                              void* d_out, int out_size) {
    (void)n_in; (void)out_size;

    const float* x = (const float*)d_in[0];
    const float *ew0, *eb0, *eg0, *ebb0;
    const float *ew1, *eg1, *ebb1;
    const float *ew2, *eg2, *ebb2;
    const float *ew3, *eb3;

    if (in_sizes[3] == 64) {
        ew0 = (const float*)d_in[1];  eb0 = (const float*)d_in[2];
        eg0 = (const float*)d_in[3];  ebb0 = (const float*)d_in[4];
        ew1 = (const float*)d_in[5];
        eg1 = (const float*)d_in[7];  ebb1 = (const float*)d_in[8];
        ew2 = (const float*)d_in[9];
        eg2 = (const float*)d_in[11]; ebb2 = (const float*)d_in[12];
        ew3 = (const float*)d_in[13]; eb3 = (const float*)d_in[14];
    } else {
        ew0 = (const float*)d_in[1];  eb0 = (const float*)d_in[2];
        ew1 = (const float*)d_in[3];
        ew2 = (const float*)d_in[5];
        ew3 = (const float*)d_in[7];  eb3 = (const float*)d_in[8];
        eg0 = (const float*)d_in[9];  ebb0 = (const float*)d_in[10];
        eg1 = (const float*)d_in[11]; ebb1 = (const float*)d_in[12];
        eg2 = (const float*)d_in[13]; ebb2 = (const float*)d_in[14];
    }

    const float* cb   = (const float*)d_in[15];
    const float* dw0  = (const float*)d_in[16];
    const float* dg0  = (const float*)d_in[18];
    const float* dbb0 = (const float*)d_in[19];
    const float* dw1  = (const float*)d_in[20];
    const float* dg1  = (const float*)d_in[22];
    const float* dbb1 = (const float*)d_in[23];
    const float* dw2  = (const float*)d_in[24];
    const float* dg2  = (const float*)d_in[26];
    const float* dbb2 = (const float*)d_in[27];
    const float* dw3  = (const float*)d_in[28];
    const float* db3  = (const float*)d_in[29];
    float* out = (float*)d_out;

    float *y0, *y1, *y2, *z, *q, *d0, *d1, *d2, *wt, *part, *sc, *sf, *cn, *rl;
    bf16 *wbh, *wbl;
    float2* bnp;
    cudaGetSymbolAddress((void**)&y0, g_y0);
    cudaGetSymbolAddress((void**)&y1, g_y1);
    cudaGetSymbolAddress((void**)&y2, g_y2);
    cudaGetSymbolAddress((void**)&z,  g_z);
    cudaGetSymbolAddress((void**)&q,  g_q);
    cudaGetSymbolAddress((void**)&d0, g_d0);
    cudaGetSymbolAddress((void**)&d1, g_d1);
    cudaGetSymbolAddress((void**)&d2, g_d2);
    cudaGetSymbolAddress((void**)&wt, g_wt);
    cudaGetSymbolAddress((void**)&part, g_part);
    cudaGetSymbolAddress((void**)&wbh, g_wbh);
    cudaGetSymbolAddress((void**)&wbl, g_wbl);
    cudaGetSymbolAddress((void**)&sc, g_scale);
    cudaGetSymbolAddress((void**)&sf, g_shift);
    cudaGetSymbolAddress((void**)&cn, g_cnorm);
    cudaGetSymbolAddress((void**)&rl, g_rowloss);
    cudaGetSymbolAddress((void**)&bnp, g_bnp);

    const long OF_E1 = 0, OF_E2 = 131072, OF_E3 = 655360;
    const long OF_D0 = 1703936, OF_D1 = 2228224, OF_D2 = 2260992;

    dim3 t32(32, 8);
    wtrans<<<dim3(2, 2), t32>>>(ew0, wt, 64, 48);
    wsplit<<<512,  256>>>(ew1, wbh + OF_E1, wbl + OF_E1, 131072);
    wsplit<<<2048, 256>>>(ew2, wbh + OF_E2, wbl + OF_E2, 524288);
    wsplit<<<4096, 256>>>(ew3, wbh + OF_E3, wbl + OF_E3, 1048576);
    wsplit_t<<<dim3(64, 8), t32>>>(dw0, wbh + OF_D0, wbl + OF_D0, 256, 2048);
    wsplit_t<<<dim3(8, 4),  t32>>>(dw1, wbh + OF_D1, wbl + OF_D1, 128, 256);
    wsplit_t<<<dim3(4, 2),  t32>>>(dw2, wbh + OF_D2, wbl + OF_D2, 64, 128);
    cnormk<<<512, 256>>>(cb, cn);

    // ---- encoder ----
    gconv<3, 64, 128, 128><<<dim3(1024, 1), 256>>>(x, wt, eb0, y0);
    bnpart<<<dim3(64, 8), 256>>>(y0, 64, 4096, bnp);
    bnfin<<<1, 64>>>(bnp, eg0, ebb0, sc + 0*256, sf + 0*256, 64, 1.f/(16.f*4096.f));

    tconv<64, 128, 64, 64, true, 2><<<dim3(128, 1, 2), 256>>>(y0, wbh + OF_E1, wbl + OF_E1, sc + 0*256, sf + 0*256, part);
    combine<<<8192, 256>>>(part, nullptr, y1, 2097152, 2, 1024, 128);
    bnpart<<<dim3(128, 8), 256>>>(y1, 128, 1024, bnp);
    bnfin<<<1, 128>>>(bnp, eg1, ebb1, sc + 1*256, sf + 1*256, 128, 1.f/(16.f*1024.f));

    tconv<128, 256, 32, 32, true, 4><<<dim3(32, 2, 4), 256>>>(y1, wbh + OF_E2, wbl + OF_E2, sc + 1*256, sf + 1*256, part);
    combine<<<4096, 256>>>(part, nullptr, y2, 1048576, 4, 256, 256);
    bnpart<<<dim3(256, 8), 256>>>(y2, 256, 256, bnp);
    bnfin<<<1, 256>>>(bnp, eg2, ebb2, sc + 2*256, sf + 2*256, 256, 1.f/(16.f*256.f));

    tconv<256, 256, 16, 16, true, 16><<<dim3(8, 2, 16), 256>>>(y2, wbh + OF_E3, wbl + OF_E3, sc + 2*256, sf + 2*256, part);
    combine<<<1024, 256>>>(part, eb3, z, 262144, 16, 64, 256);

    // ---- vector quantizer ----
    vqk<<<1024, 256>>>(z, cb, cn, q, rl, out + 786434, out + 786434 + 1024);
    lossfin<<<1, 256>>>(rl, out);

    // ---- decoder ----
    tconvt<256, 128, 4, 8, 8, false, 2><<<dim3(8, 16, 2), 256>>>(q, wbh + OF_D0, wbl + OF_D0, nullptr, nullptr, part);
    combine<<<8192, 256>>>(part, nullptr, d0, 2097152, 2, 1024, 128);
    bnpart<<<dim3(128, 8), 256>>>(d0, 128, 1024, bnp);
    bnfin<<<1, 128>>>(bnp, dg0, dbb0, sc + 3*256, sf + 3*256, 128, 1.f/(16.f*1024.f));

    tconvt<128, 64, 2, 32, 32, true, 1><<<dim3(128, 2, 1), 256>>>(d0, wbh + OF_D1, wbl + OF_D1, sc + 3*256, sf + 3*256, d1);
    bnpart<<<dim3(64, 8), 256>>>(d1, 64, 4096, bnp);
    bnfin<<<1, 64>>>(bnp, dg1, dbb1, sc + 4*256, sf + 4*256, 64, 1.f/(16.f*4096.f));

    tconvt<64, 32, 2, 64, 64, true, 1><<<dim3(512, 1, 1), 256>>>(d1, wbh + OF_D2, wbl + OF_D2, sc + 4*256, sf + 4*256, d2);
    bnpart<<<dim3(32, 8), 256>>>(d2, 32, 16384, bnp);
    bnfin<<<1, 32>>>(bnp, dg2, dbb2, sc + 5*256, sf + 5*256, 32, 1.f/(16.f*16384.f));

    final1x1<<<1024, 256>>>(d2, dw3, db3, sc + 5*256, sf + 5*256, out);
}

// round 15
// speedup vs baseline: 1.2976x; 1.2976x over previous
#include <cuda_runtime.h>
#include <cuda_bf16.h>
#include <math.h>
#include <stdint.h>

#define LEAKK 0.01f
#define EPSS  1e-5f

typedef __nv_bfloat16 bf16;

// packed fp32x2 FMA — enc0 kernel only
#define FMA2(acc, a, b) \
    asm("fma.rn.f32x2 %0, %1, %2, %0;" : "+l"(acc) : "l"(a), "l"(b))

__device__ __forceinline__ float2 unpk(unsigned long long p) {
    unsigned int lo, hi;
    asm("mov.b64 {%0,%1}, %2;" : "=r"(lo), "=r"(hi) : "l"(p));
    return make_float2(__uint_as_float(lo), __uint_as_float(hi));
}

// mma.sync m16n8k16 row.col bf16 -> f32
__device__ __forceinline__ void mma16816(float* d, const uint32_t* a,
                                         uint32_t b0, uint32_t b1) {
    asm volatile(
        "mma.sync.aligned.m16n8k16.row.col.f32.bf16.bf16.f32 "
        "{%0,%1,%2,%3}, {%4,%5,%6,%7}, {%8,%9}, {%0,%1,%2,%3};"
        : "+f"(d[0]), "+f"(d[1]), "+f"(d[2]), "+f"(d[3])
        : "r"(a[0]), "r"(a[1]), "r"(a[2]), "r"(a[3]), "r"(b0), "r"(b1));
}

// ---------------- scratch (device globals; no allocation) ----------------
__device__ float g_y0[16*64*64*64];
__device__ float g_y1[16*128*32*32];
__device__ float g_y2[16*256*16*16];
__device__ float g_z [16*256*8*8];
__device__ float g_q [16*256*8*8];
__device__ float g_d0[16*128*32*32];
__device__ float g_d1[16*64*64*64];
__device__ float g_d2[16*32*128*128];
__device__ float g_wt[4096];
__device__ float g_part[4194304];
__device__ bf16  g_wbh[2269184];
__device__ bf16  g_wbl[2269184];
__device__ float g_scale[6*256];
__device__ float g_shift[6*256];
__device__ float g_cnorm[512];
__device__ float g_rowloss[1024];
__device__ float2 g_bnp[256*8];

// ---------------- smem-tiled transpose (enc0 weights) ---------------------
__global__ void wtrans(const float* __restrict__ in, float* __restrict__ outp,
                       int R, int Ccol) {
    __shared__ float t[32][33];
    int bx = blockIdx.x * 32, by = blockIdx.y * 32;
    int tx = threadIdx.x, ty = threadIdx.y;
#pragma unroll
    for (int j = 0; j < 4; j++) {
        int xx = bx + tx, yy = by + ty + j * 8;
        if (xx < Ccol && yy < R) t[ty + j * 8][tx] = in[yy * Ccol + xx];
    }
    __syncthreads();
#pragma unroll
    for (int j = 0; j < 4; j++) {
        int xx = by + tx, yy = bx + ty + j * 8;
        if (xx < R && yy < Ccol) outp[yy * R + xx] = t[tx][ty + j * 8];
    }
}

// ---------------- weight split: fp32 -> bf16 hi/lo -------------------------
__global__ void wsplit(const float* __restrict__ w, bf16* __restrict__ h,
                       bf16* __restrict__ l, int n) {
    int i = blockIdx.x * blockDim.x + threadIdx.x;
    if (i >= n) return;
    float v = w[i];
    bf16 hh = __float2bfloat16(v);
    h[i] = hh;
    l[i] = __float2bfloat16(v - __bfloat162float(hh));
}

// ---------------- transpose + split: in[R][C] -> h/l [C][R] ----------------
__global__ void wsplit_t(const float* __restrict__ in, bf16* __restrict__ oh,
                         bf16* __restrict__ ol, int R, int C) {
    __shared__ float t[32][33];
    int bx = blockIdx.x * 32, by = blockIdx.y * 32;
    int tx = threadIdx.x, ty = threadIdx.y;
#pragma unroll
    for (int j = 0; j < 4; j++) {
        int xx = bx + tx, yy = by + ty + j * 8;
        if (xx < C && yy < R) t[ty + j * 8][tx] = in[yy * C + xx];
    }
    __syncthreads();
#pragma unroll
    for (int j = 0; j < 4; j++) {
        int cc = bx + ty + j * 8, rr = by + tx;
        if (cc < C && rr < R) {
            float v = t[tx][ty + j * 8];
            bf16 hh = __float2bfloat16(v);
            oh[cc * R + rr] = hh;
            ol[cc * R + rr] = __float2bfloat16(v - __bfloat162float(hh));
        }
    }
}

// ---------------- enc0 conv (FMA2 64x64 tile, proven) ----------------------
template<int CIN, int COUT, int H, int W>
__global__ void __launch_bounds__(256)
gconv(const float* __restrict__ x, const float* __restrict__ wt,
      const float* __restrict__ bias, float* __restrict__ out) {
    constexpr int Ho = H / 2, Wo = W / 2, HoWo = Ho * Wo;
    __shared__ float Asd[2][16][128];
    __shared__ float Bs [2][16][64];
    const int tid = threadIdx.x;
    const int tx = tid & 15, ty = tid >> 4;
    const int p0 = blockIdx.x * 64, co0 = blockIdx.y * 64;
    const int pp = tid & 63, cc = tid & 63;
    int kkj[4], boff[4]; bool val[4];
    {
        int gp = p0 + pp;
        int b = gp / HoWo, r = gp % HoWo;
        int oh = r / Wo, ow = r % Wo;
#pragma unroll
        for (int j = 0; j < 4; j++) {
            int kk = (tid >> 6) + 4 * j;
            int kh = kk >> 2, kw = kk & 3;
            int ih = 2 * oh - 1 + kh, iw = 2 * ow - 1 + kw;
            val[j] = (ih >= 0) && (ih < H) && (iw >= 0) && (iw < W);
            kkj[j] = kk;
            boff[j] = (b * CIN) * H * W + ih * W + iw;
        }
    }
    float bv[4], av[4];
    auto gather = [&](int ci) {
#pragma unroll
        for (int j = 0; j < 4; j++) {
            float v = 0.f;
            if (val[j]) v = x[boff[j] + ci * (H * W)];
            bv[j] = v;
            av[j] = wt[(ci * 16 + kkj[j]) * COUT + co0 + cc];
        }
    };
    auto stobuf = [&](int nb) {
#pragma unroll
        for (int j = 0; j < 4; j++) {
            Bs[nb][kkj[j]][pp] = bv[j];
            *(float2*)&Asd[nb][kkj[j]][2 * cc] = make_float2(av[j], av[j]);
        }
    };
    gather(0); stobuf(0);
    __syncthreads();
    unsigned long long acc[4][2];
#pragma unroll
    for (int i = 0; i < 4; i++) { acc[i][0] = 0ULL; acc[i][1] = 0ULL; }
    for (int c = 0; c < CIN; c++) {
        int cur = c & 1;
        bool more = (c + 1) < CIN;
        if (more) gather(c + 1);
#pragma unroll
        for (int k = 0; k < 16; k++) {
            ulonglong2 b2  = *(const ulonglong2*)&Bs [cur][k][4 * tx];
            ulonglong2 a01 = *(const ulonglong2*)&Asd[cur][k][8 * ty];
            ulonglong2 a23 = *(const ulonglong2*)&Asd[cur][k][8 * ty + 4];
            FMA2(acc[0][0], a01.x, b2.x); FMA2(acc[0][1], a01.x, b2.y);
            FMA2(acc[1][0], a01.y, b2.x); FMA2(acc[1][1], a01.y, b2.y);
            FMA2(acc[2][0], a23.x, b2.x); FMA2(acc[2][1], a23.x, b2.y);
            FMA2(acc[3][0], a23.y, b2.x); FMA2(acc[3][1], a23.y, b2.y);
        }
        if (more) stobuf(cur ^ 1);
        __syncthreads();
    }
    const int b = p0 / HoWo;
    const int rb = (p0 % HoWo) + 4 * tx;
#pragma unroll
    for (int i = 0; i < 4; i++) {
        int co = co0 + 4 * ty + i;
        float bvs = bias[co];
        float2 u0 = unpk(acc[i][0]);
        float2 u1 = unpk(acc[i][1]);
        *(float4*)&out[(b * COUT + co) * HoWo + rb]
            = make_float4(u0.x + bvs, u0.y + bvs, u1.x + bvs, u1.y + bvs);
    }
}

// ---------------- HMMA conv GEMM: 128px x 128co, K16 chunks, dbl-buffer ----
template<int CIN, int COUT, int H, int W, bool BN, int NSPLIT>
__global__ void __launch_bounds__(256)
tconv(const float* __restrict__ x, const bf16* __restrict__ wh,
      const bf16* __restrict__ wl,
      const float* __restrict__ scale, const float* __restrict__ shift,
      float* __restrict__ out) {
    constexpr int Ho = H / 2, Wo = W / 2, HoWo = Ho * Wo;
    constexpr int Kfull = CIN * 16;
    constexpr int Kslice = Kfull / NSPLIT;
    constexpr int NCH = Kslice / 16;
    constexpr long SLICE = (long)16 * HoWo * COUT;

    __shared__ __align__(16) bf16 AsH[2][2048], AsL[2][2048],
                                  BsH[2][2048], BsL[2][2048];

    const int tid = threadIdx.x;
    const int warp = tid >> 5, lane = tid & 31;
    const int g = lane >> 2, tg = lane & 3;
    const int m0 = warp * 16;

    const int p0 = blockIdx.x * 128;
    const int n0 = blockIdx.y * 128;
    const int k0 = blockIdx.z * Kslice;
    const int pb = tid & 127, half = tid >> 7;

    int boffs[8]; unsigned vm = 0;
    {
        int gp = p0 + pb;
        int b = gp / HoWo, r = gp % HoWo;
        int oh = r / Wo, ow = r % Wo;
        int ih0 = 2 * oh - 1, iw0 = 2 * ow - 1;
        int xbase = b * CIN * H * W;
#pragma unroll
        for (int e = 0; e < 8; e++) {
            int kk = half * 8 + e;
            int kh = kk >> 2, kw = kk & 3;
            int ih = ih0 + kh, iw = iw0 + kw;
            if (ih >= 0 && ih < H && iw >= 0 && iw < W) vm |= (1u << e);
            boffs[e] = xbase + ih * W + iw;
        }
    }

    auto fill = [&](int c, int buf) {
        {
            int ci = (k0 + c * 16) >> 4;
            float sc_ = 1.f, sf_ = 0.f;
            if (BN) { sc_ = scale[ci]; sf_ = shift[ci]; }
            const float* xch = x + (long)ci * (H * W);
            uint4 uh, ul;
            bf16* hp = (bf16*)&uh; bf16* lp = (bf16*)&ul;
#pragma unroll
            for (int e = 0; e < 8; e++) {
                float v = 0.f;
                if ((vm >> e) & 1) {
                    v = xch[boffs[e]];
                    if (BN) { v = v * sc_ + sf_; v = fmaxf(v, LEAKK * v); }
                }
                bf16 hh = __float2bfloat16(v);
                hp[e] = hh;
                lp[e] = __float2bfloat16(v - __bfloat162float(hh));
            }
            *(uint4*)&AsH[buf][pb * 16 + half * 8] = uh;
            *(uint4*)&AsL[buf][pb * 16 + half * 8] = ul;
        }
        {
            long roff = (long)(n0 + pb) * Kfull + k0 + c * 16 + half * 8;
            *(uint4*)&BsH[buf][pb * 16 + half * 8] = *(const uint4*)(wh + roff);
            *(uint4*)&BsL[buf][pb * 16 + half * 8] = *(const uint4*)(wl + roff);
        }
    };

    float acc[16][4];
#pragma unroll
    for (int nt = 0; nt < 16; nt++)
#pragma unroll
        for (int i = 0; i < 4; i++) acc[nt][i] = 0.f;

    fill(0, 0);
    __syncthreads();

    for (int c = 0; c < NCH; c++) {
        int cur = c & 1;
        if (c + 1 < NCH) fill(c + 1, cur ^ 1);
        const uint32_t* AH32 = (const uint32_t*)AsH[cur];
        const uint32_t* AL32 = (const uint32_t*)AsL[cur];
        const uint32_t* BH32 = (const uint32_t*)BsH[cur];
        const uint32_t* BL32 = (const uint32_t*)BsL[cur];
        uint32_t ah[4], al[4];
        ah[0] = AH32[(m0 + g) * 8 + tg];     ah[1] = AH32[(m0 + g + 8) * 8 + tg];
        ah[2] = AH32[(m0 + g) * 8 + tg + 4]; ah[3] = AH32[(m0 + g + 8) * 8 + tg + 4];
        al[0] = AL32[(m0 + g) * 8 + tg];     al[1] = AL32[(m0 + g + 8) * 8 + tg];
        al[2] = AL32[(m0 + g) * 8 + tg + 4]; al[3] = AL32[(m0 + g + 8) * 8 + tg + 4];
#pragma unroll
        for (int nt = 0; nt < 16; nt++) {
            int nr = nt * 8 + g;
            uint32_t bh0 = BH32[nr * 8 + tg], bh1 = BH32[nr * 8 + tg + 4];
            uint32_t bl0 = BL32[nr * 8 + tg], bl1 = BL32[nr * 8 + tg + 4];
            mma16816(acc[nt], ah, bh0, bh1);
            mma16816(acc[nt], ah, bl0, bl1);
            mma16816(acc[nt], al, bh0, bh1);
        }
        __syncthreads();
    }

    float* po = out + (NSPLIT > 1 ? (long)blockIdx.z * SLICE : 0);
    const int r0 = p0 + m0 + g, r1 = r0 + 8;
    const int b0_ = r0 / HoWo, ri0 = r0 % HoWo;
    const int b1_ = r1 / HoWo, ri1 = r1 % HoWo;
#pragma unroll
    for (int nt = 0; nt < 16; nt++) {
        int co = n0 + nt * 8 + 2 * tg;
        po[((long)(b0_ * COUT + co)) * HoWo + ri0]     = acc[nt][0];
        po[((long)(b0_ * COUT + co + 1)) * HoWo + ri0] = acc[nt][1];
        po[((long)(b1_ * COUT + co)) * HoWo + ri1]     = acc[nt][2];
        po[((long)(b1_ * COUT + co + 1)) * HoWo + ri1] = acc[nt][3];
    }
}

// ---------------- HMMA convt GEMM: 128px x 128m, K16, dbl-buffer -----------
template<int CIN, int COUT, int KS, int H, int W, bool BN, int NSPLIT>
__global__ void __launch_bounds__(256)
tconvt(const float* __restrict__ x, const bf16* __restrict__ wh,
       const bf16* __restrict__ wl,
       const float* __restrict__ scale, const float* __restrict__ shift,
       float* __restrict__ out) {
    constexpr int HW = H * W;
    constexpr int KK = KS * KS;
    constexpr int Hout = H * KS, Wout = W * KS;
    constexpr int Kslice = CIN / NSPLIT;
    constexpr int NCH = Kslice / 16;
    constexpr long SLICE = (long)16 * COUT * Hout * Wout;

    __shared__ __align__(16) bf16 AsH[2][2048], AsL[2][2048],
                                  BsH[2][2048], BsL[2][2048];

    const int tid = threadIdx.x;
    const int warp = tid >> 5, lane = tid & 31;
    const int g = lane >> 2, tg = lane & 3;
    const int m0 = warp * 16;

    const int p0 = blockIdx.x * 128;
    const int n0 = blockIdx.y * 128;
    const int cbase = blockIdx.z * Kslice;
    const int pb = tid & 127, half = tid >> 7;

    const int gp = p0 + pb;
    const int bI0 = gp / HW, rI0 = gp % HW;
    const long xrow = (long)bI0 * CIN * HW + rI0;

    auto fill = [&](int c, int buf) {
        {
            int cs = cbase + c * 16 + half * 8;
            uint4 uh, ul;
            bf16* hp = (bf16*)&uh; bf16* lp = (bf16*)&ul;
#pragma unroll
            for (int e = 0; e < 8; e++) {
                int ci = cs + e;
                float v = x[xrow + (long)ci * HW];
                if (BN) {
                    float t = v * scale[ci] + shift[ci];
                    v = fmaxf(t, LEAKK * t);
                }
                bf16 hh = __float2bfloat16(v);
                hp[e] = hh;
                lp[e] = __float2bfloat16(v - __bfloat162float(hh));
            }
            *(uint4*)&AsH[buf][pb * 16 + half * 8] = uh;
            *(uint4*)&AsL[buf][pb * 16 + half * 8] = ul;
        }
        {
            long roff = (long)(n0 + pb) * CIN + cbase + c * 16 + half * 8;
            *(uint4*)&BsH[buf][pb * 16 + half * 8] = *(const uint4*)(wh + roff);
            *(uint4*)&BsL[buf][pb * 16 + half * 8] = *(const uint4*)(wl + roff);
        }
    };

    float acc[16][4];
#pragma unroll
    for (int nt = 0; nt < 16; nt++)
#pragma unroll
        for (int i = 0; i < 4; i++) acc[nt][i] = 0.f;

    fill(0, 0);
    __syncthreads();

    for (int c = 0; c < NCH; c++) {
        int cur = c & 1;
        if (c + 1 < NCH) fill(c + 1, cur ^ 1);
        const uint32_t* AH32 = (const uint32_t*)AsH[cur];
        const uint32_t* AL32 = (const uint32_t*)AsL[cur];
        const uint32_t* BH32 = (const uint32_t*)BsH[cur];
        const uint32_t* BL32 = (const uint32_t*)BsL[cur];
        uint32_t ah[4], al[4];
        ah[0] = AH32[(m0 + g) * 8 + tg];     ah[1] = AH32[(m0 + g + 8) * 8 + tg];
        ah[2] = AH32[(m0 + g) * 8 + tg + 4]; ah[3] = AH32[(m0 + g + 8) * 8 + tg + 4];
        al[0] = AL32[(m0 + g) * 8 + tg];     al[1] = AL32[(m0 + g + 8) * 8 + tg];
        al[2] = AL32[(m0 + g) * 8 + tg + 4]; al[3] = AL32[(m0 + g + 8) * 8 + tg + 4];
#pragma unroll
        for (int nt = 0; nt < 16; nt++) {
            int nr = nt * 8 + g;
            uint32_t bh0 = BH32[nr * 8 + tg], bh1 = BH32[nr * 8 + tg + 4];
            uint32_t bl0 = BL32[nr * 8 + tg], bl1 = BL32[nr * 8 + tg + 4];
            mma16816(acc[nt], ah, bh0, bh1);
            mma16816(acc[nt], ah, bl0, bl1);
            mma16816(acc[nt], al, bh0, bh1);
        }
        __syncthreads();
    }

    float* po = out + (NSPLIT > 1 ? (long)blockIdx.z * SLICE : 0);
    const int r0 = p0 + m0 + g, r1 = r0 + 8;
    const int b0_ = r0 / HW, ri0 = r0 % HW;
    const int b1_ = r1 / HW, ri1 = r1 % HW;
    const int ih0 = ri0 / W, iw0 = ri0 % W;
    const int ih1 = ri1 / W, iw1 = ri1 % W;
#pragma unroll
    for (int nt = 0; nt < 16; nt++) {
        int n = n0 + nt * 8 + 2 * tg;
#pragma unroll
        for (int l = 0; l < 2; l++) {
            int nn = n + l;
            int co = nn / KK, rem = nn % KK;
            int ki = rem / KS, kj = rem % KS;
            po[((long)(b0_ * COUT + co) * Hout + ih0 * KS + ki) * Wout + iw0 * KS + kj]
                = acc[nt][l];
            po[((long)(b1_ * COUT + co) * Hout + ih1 * KS + ki) * Wout + iw1 * KS + kj]
                = acc[nt][2 + l];
        }
    }
}

// ---------------- K-split combine (nullable bias) ---------------------------
__global__ void combine(const float* __restrict__ part, const float* __restrict__ bias,
                        float* __restrict__ out, int len, int S, int HWo, int CO) {
    int i = blockIdx.x * blockDim.x + threadIdx.x;
    if (i >= len) return;
    float s = 0.f;
    for (int k = 0; k < S; k++) s += part[i + (long)k * len];
    float bv = bias ? bias[(i / HWo) % CO] : 0.f;
    out[i] = s + bv;
}

// ---------------- BN batch stats (two-phase) --------------------------------
__global__ void bnpart(const float* __restrict__ y, int C, int HW,
                       float2* __restrict__ part) {
    int c = blockIdx.x, s = blockIdx.y;
    int seg = HW / 8, r0 = s * seg;
    float sm = 0.f, s2 = 0.f;
    for (int b = 0; b < 16; b++) {
        const float* p = y + (long)(b * C + c) * HW;
        for (int r = r0 + threadIdx.x; r < r0 + seg; r += 256) {
            float v = p[r];
            sm += v; s2 += v * v;
        }
    }
    __shared__ float sh[256], sh2[256];
    sh[threadIdx.x] = sm; sh2[threadIdx.x] = s2;
    __syncthreads();
    for (int o = 128; o > 0; o >>= 1) {
        if (threadIdx.x < o) { sh[threadIdx.x] += sh[threadIdx.x + o];
                               sh2[threadIdx.x] += sh2[threadIdx.x + o]; }
        __syncthreads();
    }
    if (threadIdx.x == 0) part[c * 8 + s] = make_float2(sh[0], sh2[0]);
}

__global__ void bnfin(const float2* __restrict__ part,
                      const float* __restrict__ g, const float* __restrict__ bb,
                      float* __restrict__ scale, float* __restrict__ shift,
                      int C, float invn) {
    int c = threadIdx.x;
    if (c >= C) return;
    float sm = 0.f, s2 = 0.f;
#pragma unroll
    for (int s = 0; s < 8; s++) { float2 p = part[c * 8 + s]; sm += p.x; s2 += p.y; }
    float m = sm * invn;
    float v = s2 * invn - m * m;
    float sc = g[c] * rsqrtf(v + EPSS);
    scale[c] = sc;
    shift[c] = bb[c] - m * sc;
}

// ---------------- codebook squared norms ------------------------------------
__global__ void cnormk(const float* __restrict__ cb, float* __restrict__ cn) {
    int c = blockIdx.x;
    float v = cb[c * 256 + threadIdx.x];
    __shared__ float sh[256];
    sh[threadIdx.x] = v * v;
    __syncthreads();
    for (int o = 128; o > 0; o >>= 1) {
        if (threadIdx.x < o) sh[threadIdx.x] += sh[threadIdx.x + o];
        __syncthreads();
    }
    if (threadIdx.x == 0) cn[c] = sh[0];
}

// ---------------- vector quantizer ------------------------------------------
__global__ void vqk(const float* __restrict__ z, const float* __restrict__ cb,
                    const float* __restrict__ cn, float* __restrict__ q,
                    float* __restrict__ rowloss,
                    float* __restrict__ out_idx, float* __restrict__ out_mind) {
    int row = blockIdx.x;
    int b = row >> 6, hw = row & 63;
    int tid = threadIdx.x, lane = tid & 31, warp = tid >> 5;
    __shared__ float zf[256];
    __shared__ float red[256];

    zf[tid] = z[(b * 256 + tid) * 64 + hw];
    red[tid] = zf[tid] * zf[tid];
    __syncthreads();
    for (int o = 128; o > 0; o >>= 1) {
        if (tid < o) red[tid] += red[tid + o];
        __syncthreads();
    }
    float znorm = red[0];
    __syncthreads();

    float best = 3.4e38f; int bidx = 1 << 20;
    for (int code = warp; code < 512; code += 8) {
        const float* cr = cb + code * 256;
        float dot = 0.f;
#pragma unroll
        for (int k = 0; k < 8; k++) dot += cr[lane + 32 * k] * zf[lane + 32 * k];
#pragma unroll
        for (int o = 16; o > 0; o >>= 1) dot += __shfl_down_sync(0xffffffffu, dot, o);
        if (lane == 0) {
            float d2 = znorm - 2.f * dot + cn[code];
            if (d2 < best || (d2 == best && code < bidx)) { best = d2; bidx = code; }
        }
    }
    __shared__ float wbest[8]; __shared__ int widx[8];
    if (lane == 0) { wbest[warp] = best; widx[warp] = bidx; }
    __syncthreads();
    if (tid == 0) {
        float bb = wbest[0]; int bi = widx[0];
        for (int w = 1; w < 8; w++)
            if (wbest[w] < bb || (wbest[w] == bb && widx[w] < bi)) { bb = wbest[w]; bi = widx[w]; }
        wbest[0] = bb; widx[0] = bi;
    }
    __syncthreads();
    int idx = widx[0];
    float mind = wbest[0];

    float qv = cb[idx * 256 + tid];
    q[(b * 256 + tid) * 64 + hw] = qv;
    float diff = qv - zf[tid];
    red[tid] = diff * diff;
    __syncthreads();
    for (int o = 128; o > 0; o >>= 1) {
        if (tid < o) red[tid] += red[tid + o];
        __syncthreads();
    }
    if (tid == 0) {
        rowloss[row] = red[0];
        out_idx[row] = (float)idx;
        out_mind[row] = mind;
    }
}

__global__ void lossfin(const float* __restrict__ rowloss, float* __restrict__ out) {
    __shared__ float sh[256];
    float s = 0.f;
    for (int i = threadIdx.x; i < 1024; i += 256) s += rowloss[i];
    sh[threadIdx.x] = s; __syncthreads();
    for (int o = 128; o > 0; o >>= 1) {
        if (threadIdx.x < o) sh[threadIdx.x] += sh[threadIdx.x + o];
        __syncthreads();
    }
    if (threadIdx.x == 0) {
        float L = sh[0] / (1024.f * 256.f);
        out[786432] = L;
        out[786433] = L;
    }
}

// ---------------- final 1x1 conv + tanh -------------------------------------
__global__ void final1x1(const float* __restrict__ h, const float* __restrict__ w3,
                         const float* __restrict__ b3,
                         const float* __restrict__ scale, const float* __restrict__ shift,
                         float* __restrict__ out) {
    __shared__ float sw[96], ssc[32], ssh[32], sb[3];
    if (threadIdx.x < 96) sw[threadIdx.x] = w3[threadIdx.x];
    if (threadIdx.x < 32) { ssc[threadIdx.x] = scale[threadIdx.x];
                            ssh[threadIdx.x] = shift[threadIdx.x]; }
    if (threadIdx.x < 3) sb[threadIdx.x] = b3[threadIdx.x];
    __syncthreads();
    const int HW = 128 * 128;
    int gid = blockIdx.x * blockDim.x + threadIdx.x;
    int b = gid / HW, r = gid % HW;
    float a0 = 0.f, a1 = 0.f, a2 = 0.f;
#pragma unroll 8
    for (int c = 0; c < 32; c++) {
        float v = h[(b * 32 + c) * HW + r];
        v = v * ssc[c] + ssh[c];
        v = fmaxf(v, LEAKK * v);
        a0 += v * sw[c];
        a1 += v * sw[32 + c];
        a2 += v * sw[64 + c];
    }
    out[(b * 3 + 0) * HW + r] = tanhf(a0 + sb[0]);
    out[(b * 3 + 1) * HW + r] = tanhf(a1 + sb[1]);
    out[(b * 3 + 2) * HW + r] = tanhf(a2 + sb[2]);
}

// ----------------------------------------------------------------------------
extern "C" void kernel_launch(void* const* d_in, const int* in_sizes, int n_in,
                              void* d_out, int out_size) {
    (void)n_in; (void)out_size;

    const float* x = (const float*)d_in[0];
    const float *ew0, *eb0, *eg0, *ebb0;
    const float *ew1, *eg1, *ebb1;
    const float *ew2, *eg2, *ebb2;
    const float *ew3, *eb3;

    if (in_sizes[3] == 64) {
        ew0 = (const float*)d_in[1];  eb0 = (const float*)d_in[2];
        eg0 = (const float*)d_in[3];  ebb0 = (const float*)d_in[4];
        ew1 = (const float*)d_in[5];
        eg1 = (const float*)d_in[7];  ebb1 = (const float*)d_in[8];
        ew2 = (const float*)d_in[9];
        eg2 = (const float*)d_in[11]; ebb2 = (const float*)d_in[12];
        ew3 = (const float*)d_in[13]; eb3 = (const float*)d_in[14];
    } else {
        ew0 = (const float*)d_in[1];  eb0 = (const float*)d_in[2];
        ew1 = (const float*)d_in[3];
        ew2 = (const float*)d_in[5];
        ew3 = (const float*)d_in[7];  eb3 = (const float*)d_in[8];
        eg0 = (const float*)d_in[9];  ebb0 = (const float*)d_in[10];
        eg1 = (const float*)d_in[11]; ebb1 = (const float*)d_in[12];
        eg2 = (const float*)d_in[13]; ebb2 = (const float*)d_in[14];
    }

    const float* cb   = (const float*)d_in[15];
    const float* dw0  = (const float*)d_in[16];
    const float* dg0  = (const float*)d_in[18];
    const float* dbb0 = (const float*)d_in[19];
    const float* dw1  = (const float*)d_in[20];
    const float* dg1  = (const float*)d_in[22];
    const float* dbb1 = (const float*)d_in[23];
    const float* dw2  = (const float*)d_in[24];
    const float* dg2  = (const float*)d_in[26];
    const float* dbb2 = (const float*)d_in[27];
    const float* dw3  = (const float*)d_in[28];
    const float* db3  = (const float*)d_in[29];
    float* out = (float*)d_out;

    float *y0, *y1, *y2, *z, *q, *d0, *d1, *d2, *wt, *part, *sc, *sf, *cn, *rl;
    bf16 *wbh, *wbl;
    float2* bnp;
    cudaGetSymbolAddress((void**)&y0, g_y0);
    cudaGetSymbolAddress((void**)&y1, g_y1);
    cudaGetSymbolAddress((void**)&y2, g_y2);
    cudaGetSymbolAddress((void**)&z,  g_z);
    cudaGetSymbolAddress((void**)&q,  g_q);
    cudaGetSymbolAddress((void**)&d0, g_d0);
    cudaGetSymbolAddress((void**)&d1, g_d1);
    cudaGetSymbolAddress((void**)&d2, g_d2);
    cudaGetSymbolAddress((void**)&wt, g_wt);
    cudaGetSymbolAddress((void**)&part, g_part);
    cudaGetSymbolAddress((void**)&wbh, g_wbh);
    cudaGetSymbolAddress((void**)&wbl, g_wbl);
    cudaGetSymbolAddress((void**)&sc, g_scale);
    cudaGetSymbolAddress((void**)&sf, g_shift);
    cudaGetSymbolAddress((void**)&cn, g_cnorm);
    cudaGetSymbolAddress((void**)&rl, g_rowloss);
    cudaGetSymbolAddress((void**)&bnp, g_bnp);

    const long OF_E1 = 0, OF_E2 = 131072, OF_E3 = 655360;
    const long OF_D0 = 1703936, OF_D1 = 2228224, OF_D2 = 2260992;

    dim3 t32(32, 8);
    wtrans<<<dim3(2, 2), t32>>>(ew0, wt, 64, 48);
    wsplit<<<512,  256>>>(ew1, wbh + OF_E1, wbl + OF_E1, 131072);
    wsplit<<<2048, 256>>>(ew2, wbh + OF_E2, wbl + OF_E2, 524288);
    wsplit<<<4096, 256>>>(ew3, wbh + OF_E3, wbl + OF_E3, 1048576);
    wsplit_t<<<dim3(64, 8), t32>>>(dw0, wbh + OF_D0, wbl + OF_D0, 256, 2048);
    wsplit_t<<<dim3(8, 4),  t32>>>(dw1, wbh + OF_D1, wbl + OF_D1, 128, 256);
    wsplit_t<<<dim3(4, 2),  t32>>>(dw2, wbh + OF_D2, wbl + OF_D2, 64, 128);
    cnormk<<<512, 256>>>(cb, cn);

    // ---- encoder ----
    gconv<3, 64, 128, 128><<<dim3(1024, 1), 256>>>(x, wt, eb0, y0);
    bnpart<<<dim3(64, 8), 256>>>(y0, 64, 4096, bnp);
    bnfin<<<1, 64>>>(bnp, eg0, ebb0, sc + 0*256, sf + 0*256, 64, 1.f/(16.f*4096.f));

    tconv<64, 128, 64, 64, true, 2><<<dim3(128, 1, 2), 256>>>(y0, wbh + OF_E1, wbl + OF_E1, sc + 0*256, sf + 0*256, part);
    combine<<<8192, 256>>>(part, nullptr, y1, 2097152, 2, 1024, 128);
    bnpart<<<dim3(128, 8), 256>>>(y1, 128, 1024, bnp);
    bnfin<<<1, 128>>>(bnp, eg1, ebb1, sc + 1*256, sf + 1*256, 128, 1.f/(16.f*1024.f));

    tconv<128, 256, 32, 32, true, 4><<<dim3(32, 2, 4), 256>>>(y1, wbh + OF_E2, wbl + OF_E2, sc + 1*256, sf + 1*256, part);
    combine<<<4096, 256>>>(part, nullptr, y2, 1048576, 4, 256, 256);
    bnpart<<<dim3(256, 8), 256>>>(y2, 256, 256, bnp);
    bnfin<<<1, 256>>>(bnp, eg2, ebb2, sc + 2*256, sf + 2*256, 256, 1.f/(16.f*256.f));

    tconv<256, 256, 16, 16, true, 16><<<dim3(8, 2, 16), 256>>>(y2, wbh + OF_E3, wbl + OF_E3, sc + 2*256, sf + 2*256, part);
    combine<<<1024, 256>>>(part, eb3, z, 262144, 16, 64, 256);

    // ---- vector quantizer ----
    vqk<<<1024, 256>>>(z, cb, cn, q, rl, out + 786434, out + 786434 + 1024);
    lossfin<<<1, 256>>>(rl, out);

    // ---- decoder ----
    tconvt<256, 128, 4, 8, 8, false, 2><<<dim3(8, 16, 2), 256>>>(q, wbh + OF_D0, wbl + OF_D0, nullptr, nullptr, part);
    combine<<<8192, 256>>>(part, nullptr, d0, 2097152, 2, 1024, 128);
    bnpart<<<dim3(128, 8), 256>>>(d0, 128, 1024, bnp);
    bnfin<<<1, 128>>>(bnp, dg0, dbb0, sc + 3*256, sf + 3*256, 128, 1.f/(16.f*1024.f));

    tconvt<128, 64, 2, 32, 32, true, 1><<<dim3(128, 2, 1), 256>>>(d0, wbh + OF_D1, wbl + OF_D1, sc + 3*256, sf + 3*256, d1);
    bnpart<<<dim3(64, 8), 256>>>(d1, 64, 4096, bnp);
    bnfin<<<1, 64>>>(bnp, dg1, dbb1, sc + 4*256, sf + 4*256, 64, 1.f/(16.f*4096.f));

    tconvt<64, 32, 2, 64, 64, true, 1><<<dim3(512, 1, 1), 256>>>(d1, wbh + OF_D2, wbl + OF_D2, sc + 4*256, sf + 4*256, d2);
    bnpart<<<dim3(32, 8), 256>>>(d2, 32, 16384, bnp);
    bnfin<<<1, 32>>>(bnp, dg2, dbb2, sc + 5*256, sf + 5*256, 32, 1.f/(16.f*16384.f));

    final1x1<<<1024, 256>>>(d2, dw3, db3, sc + 5*256, sf + 5*256, out);
}

// round 16
// speedup vs baseline: 1.3295x; 1.0246x over previous
#include <cuda_runtime.h>
#include <cuda_bf16.h>
#include <math.h>
#include <stdint.h>

#define LEAKK 0.01f
#define EPSS  1e-5f

typedef __nv_bfloat16 bf16;

// packed fp32x2 FMA — enc0 kernel only
#define FMA2(acc, a, b) \
    asm("fma.rn.f32x2 %0, %1, %2, %0;" : "+l"(acc) : "l"(a), "l"(b))

__device__ __forceinline__ float2 unpk(unsigned long long p) {
    unsigned int lo, hi;
    asm("mov.b64 {%0,%1}, %2;" : "=r"(lo), "=r"(hi) : "l"(p));
    return make_float2(__uint_as_float(lo), __uint_as_float(hi));
}

// mma.sync m16n8k16 row.col bf16 -> f32
__device__ __forceinline__ void mma16816(float* d, const uint32_t* a,
                                         uint32_t b0, uint32_t b1) {
    asm volatile(
        "mma.sync.aligned.m16n8k16.row.col.f32.bf16.bf16.f32 "
        "{%0,%1,%2,%3}, {%4,%5,%6,%7}, {%8,%9}, {%0,%1,%2,%3};"
        : "+f"(d[0]), "+f"(d[1]), "+f"(d[2]), "+f"(d[3])
        : "r"(a[0]), "r"(a[1]), "r"(a[2]), "r"(a[3]), "r"(b0), "r"(b1));
}

// ldmatrix x4 (b16, no trans)
#define LDSM4(r, addr) \
    asm volatile("ldmatrix.sync.aligned.m8n8.x4.shared.b16 {%0,%1,%2,%3}, [%4];" \
        : "=r"((r)[0]), "=r"((r)[1]), "=r"((r)[2]), "=r"((r)[3]) : "r"(addr))

// ---------------- scratch (device globals; no allocation) ----------------
__device__ float g_y0[16*64*64*64];
__device__ float g_y1[16*128*32*32];
__device__ float g_y2[16*256*16*16];
__device__ float g_z [16*256*8*8];
__device__ float g_q [16*256*8*8];
__device__ float g_d0[16*128*32*32];
__device__ float g_d1[16*64*64*64];
__device__ float g_d2[16*32*128*128];
__device__ float g_wt[4096];
__device__ float g_part[4194304];
__device__ bf16  g_wbh[2269184];
__device__ bf16  g_wbl[2269184];
__device__ float g_scale[6*256];
__device__ float g_shift[6*256];
__device__ float g_cnorm[512];
__device__ float g_rowloss[1024];
__device__ float2 g_bnp[256*8];

// ---------------- smem-tiled transpose (enc0 weights) ---------------------
__global__ void wtrans(const float* __restrict__ in, float* __restrict__ outp,
                       int R, int Ccol) {
    __shared__ float t[32][33];
    int bx = blockIdx.x * 32, by = blockIdx.y * 32;
    int tx = threadIdx.x, ty = threadIdx.y;
#pragma unroll
    for (int j = 0; j < 4; j++) {
        int xx = bx + tx, yy = by + ty + j * 8;
        if (xx < Ccol && yy < R) t[ty + j * 8][tx] = in[yy * Ccol + xx];
    }
    __syncthreads();
#pragma unroll
    for (int j = 0; j < 4; j++) {
        int xx = by + tx, yy = bx + ty + j * 8;
        if (xx < R && yy < Ccol) outp[yy * R + xx] = t[tx][ty + j * 8];
    }
}

// ---------------- weight split: fp32 -> bf16 hi/lo -------------------------
__global__ void wsplit(const float* __restrict__ w, bf16* __restrict__ h,
                       bf16* __restrict__ l, int n) {
    int i = blockIdx.x * blockDim.x + threadIdx.x;
    if (i >= n) return;
    float v = w[i];
    bf16 hh = __float2bfloat16(v);
    h[i] = hh;
    l[i] = __float2bfloat16(v - __bfloat162float(hh));
}

// ---------------- transpose + split: in[R][C] -> h/l [C][R] ----------------
__global__ void wsplit_t(const float* __restrict__ in, bf16* __restrict__ oh,
                         bf16* __restrict__ ol, int R, int C) {
    __shared__ float t[32][33];
    int bx = blockIdx.x * 32, by = blockIdx.y * 32;
    int tx = threadIdx.x, ty = threadIdx.y;
#pragma unroll
    for (int j = 0; j < 4; j++) {
        int xx = bx + tx, yy = by + ty + j * 8;
        if (xx < C && yy < R) t[ty + j * 8][tx] = in[yy * C + xx];
    }
    __syncthreads();
#pragma unroll
    for (int j = 0; j < 4; j++) {
        int cc = bx + ty + j * 8, rr = by + tx;
        if (cc < C && rr < R) {
            float v = t[tx][ty + j * 8];
            bf16 hh = __float2bfloat16(v);
            oh[cc * R + rr] = hh;
            ol[cc * R + rr] = __float2bfloat16(v - __bfloat162float(hh));
        }
    }
}

// ---------------- enc0 conv (FMA2 64x64 tile, proven) ----------------------
template<int CIN, int COUT, int H, int W>
__global__ void __launch_bounds__(256)
gconv(const float* __restrict__ x, const float* __restrict__ wt,
      const float* __restrict__ bias, float* __restrict__ out) {
    constexpr int Ho = H / 2, Wo = W / 2, HoWo = Ho * Wo;
    __shared__ float Asd[2][16][128];
    __shared__ float Bs [2][16][64];
    const int tid = threadIdx.x;
    const int tx = tid & 15, ty = tid >> 4;
    const int p0 = blockIdx.x * 64, co0 = blockIdx.y * 64;
    const int pp = tid & 63, cc = tid & 63;
    int kkj[4], boff[4]; bool val[4];
    {
        int gp = p0 + pp;
        int b = gp / HoWo, r = gp % HoWo;
        int oh = r / Wo, ow = r % Wo;
#pragma unroll
        for (int j = 0; j < 4; j++) {
            int kk = (tid >> 6) + 4 * j;
            int kh = kk >> 2, kw = kk & 3;
            int ih = 2 * oh - 1 + kh, iw = 2 * ow - 1 + kw;
            val[j] = (ih >= 0) && (ih < H) && (iw >= 0) && (iw < W);
            kkj[j] = kk;
            boff[j] = (b * CIN) * H * W + ih * W + iw;
        }
    }
    float bv[4], av[4];
    auto gather = [&](int ci) {
#pragma unroll
        for (int j = 0; j < 4; j++) {
            float v = 0.f;
            if (val[j]) v = x[boff[j] + ci * (H * W)];
            bv[j] = v;
            av[j] = wt[(ci * 16 + kkj[j]) * COUT + co0 + cc];
        }
    };
    auto stobuf = [&](int nb) {
#pragma unroll
        for (int j = 0; j < 4; j++) {
            Bs[nb][kkj[j]][pp] = bv[j];
            *(float2*)&Asd[nb][kkj[j]][2 * cc] = make_float2(av[j], av[j]);
        }
    };
    gather(0); stobuf(0);
    __syncthreads();
    unsigned long long acc[4][2];
#pragma unroll
    for (int i = 0; i < 4; i++) { acc[i][0] = 0ULL; acc[i][1] = 0ULL; }
    for (int c = 0; c < CIN; c++) {
        int cur = c & 1;
        bool more = (c + 1) < CIN;
        if (more) gather(c + 1);
#pragma unroll
        for (int k = 0; k < 16; k++) {
            ulonglong2 b2  = *(const ulonglong2*)&Bs [cur][k][4 * tx];
            ulonglong2 a01 = *(const ulonglong2*)&Asd[cur][k][8 * ty];
            ulonglong2 a23 = *(const ulonglong2*)&Asd[cur][k][8 * ty + 4];
            FMA2(acc[0][0], a01.x, b2.x); FMA2(acc[0][1], a01.x, b2.y);
            FMA2(acc[1][0], a01.y, b2.x); FMA2(acc[1][1], a01.y, b2.y);
            FMA2(acc[2][0], a23.x, b2.x); FMA2(acc[2][1], a23.x, b2.y);
            FMA2(acc[3][0], a23.y, b2.x); FMA2(acc[3][1], a23.y, b2.y);
        }
        if (more) stobuf(cur ^ 1);
        __syncthreads();
    }
    const int b = p0 / HoWo;
    const int rb = (p0 % HoWo) + 4 * tx;
#pragma unroll
    for (int i = 0; i < 4; i++) {
        int co = co0 + 4 * ty + i;
        float bvs = bias[co];
        float2 u0 = unpk(acc[i][0]);
        float2 u1 = unpk(acc[i][1]);
        *(float4*)&out[(b * COUT + co) * HoWo + rb]
            = make_float4(u0.x + bvs, u0.y + bvs, u1.x + bvs, u1.y + bvs);
    }
}

// PITCH: 24 bf16 (48B) rows — conflict-free for ldmatrix phases
#define PIT 24

// ---------------- HMMA conv GEMM: 128px x 128co, ldmatrix, dbl-buffer ------
template<int CIN, int COUT, int H, int W, bool BN, int NSPLIT>
__global__ void __launch_bounds__(256)
tconv(const float* __restrict__ x, const bf16* __restrict__ wh,
      const bf16* __restrict__ wl,
      const float* __restrict__ scale, const float* __restrict__ shift,
      float* __restrict__ out) {
    constexpr int Ho = H / 2, Wo = W / 2, HoWo = Ho * Wo;
    constexpr int Kfull = CIN * 16;
    constexpr int Kslice = Kfull / NSPLIT;
    constexpr int NCH = Kslice / 16;
    constexpr long SLICE = (long)16 * HoWo * COUT;

    __shared__ __align__(16) bf16 AsH[2][128 * PIT], AsL[2][128 * PIT],
                                  BsH[2][128 * PIT], BsL[2][128 * PIT];

    const int tid = threadIdx.x;
    const int warp = tid >> 5, lane = tid & 31;
    const int g = lane >> 2, tg = lane & 3;
    const int m0 = warp * 16;

    const int p0 = blockIdx.x * 128;
    const int n0 = blockIdx.y * 128;
    const int k0 = blockIdx.z * Kslice;
    const int pb = tid & 127, half = tid >> 7;

    // per-lane ldmatrix byte offsets
    const int aoff = (lane < 16 ? (m0 + lane) * 48 : (m0 + lane - 16) * 48 + 16);
    const int boffl = (lane < 16 ? lane * 48 : (lane - 16) * 48 + 16);
    const uint32_t baseAH0 = (uint32_t)__cvta_generic_to_shared(AsH[0]);
    const uint32_t baseAH1 = (uint32_t)__cvta_generic_to_shared(AsH[1]);
    const uint32_t baseAL0 = (uint32_t)__cvta_generic_to_shared(AsL[0]);
    const uint32_t baseAL1 = (uint32_t)__cvta_generic_to_shared(AsL[1]);
    const uint32_t baseBH0 = (uint32_t)__cvta_generic_to_shared(BsH[0]);
    const uint32_t baseBH1 = (uint32_t)__cvta_generic_to_shared(BsH[1]);
    const uint32_t baseBL0 = (uint32_t)__cvta_generic_to_shared(BsL[0]);
    const uint32_t baseBL1 = (uint32_t)__cvta_generic_to_shared(BsL[1]);

    int boffs[8]; unsigned vm = 0;
    {
        int gp = p0 + pb;
        int b = gp / HoWo, r = gp % HoWo;
        int oh = r / Wo, ow = r % Wo;
        int ih0 = 2 * oh - 1, iw0 = 2 * ow - 1;
        int xbase = b * CIN * H * W;
#pragma unroll
        for (int e = 0; e < 8; e++) {
            int kk = half * 8 + e;
            int kh = kk >> 2, kw = kk & 3;
            int ih = ih0 + kh, iw = iw0 + kw;
            if (ih >= 0 && ih < H && iw >= 0 && iw < W) vm |= (1u << e);
            boffs[e] = xbase + ih * W + iw;
        }
    }

    auto fill = [&](int c, int buf) {
        {
            int ci = (k0 + c * 16) >> 4;
            float sc_ = 1.f, sf_ = 0.f;
            if (BN) { sc_ = scale[ci]; sf_ = shift[ci]; }
            const float* xch = x + (long)ci * (H * W);
            uint4 uh, ul;
            bf16* hp = (bf16*)&uh; bf16* lp = (bf16*)&ul;
#pragma unroll
            for (int e = 0; e < 8; e++) {
                float v = 0.f;
                if ((vm >> e) & 1) {
                    v = xch[boffs[e]];
                    if (BN) { v = v * sc_ + sf_; v = fmaxf(v, LEAKK * v); }
                }
                bf16 hh = __float2bfloat16(v);
                hp[e] = hh;
                lp[e] = __float2bfloat16(v - __bfloat162float(hh));
            }
            int off = pb * PIT + half * 8;
            *(uint4*)&AsH[buf][off] = uh;
            *(uint4*)&AsL[buf][off] = ul;
        }
        {
            long roff = (long)(n0 + pb) * Kfull + k0 + c * 16 + half * 8;
            int off = pb * PIT + half * 8;
            *(uint4*)&BsH[buf][off] = *(const uint4*)(wh + roff);
            *(uint4*)&BsL[buf][off] = *(const uint4*)(wl + roff);
        }
    };

    float acc[16][4];
#pragma unroll
    for (int nt = 0; nt < 16; nt++)
#pragma unroll
        for (int i = 0; i < 4; i++) acc[nt][i] = 0.f;

    fill(0, 0);
    __syncthreads();

    for (int c = 0; c < NCH; c++) {
        int cur = c & 1;
        if (c + 1 < NCH) fill(c + 1, cur ^ 1);
        uint32_t aH = (cur ? baseAH1 : baseAH0) + aoff;
        uint32_t aL = (cur ? baseAL1 : baseAL0) + aoff;
        uint32_t bH = (cur ? baseBH1 : baseBH0) + boffl;
        uint32_t bL = (cur ? baseBL1 : baseBL0) + boffl;
        uint32_t ah[4], al[4];
        LDSM4(ah, aH);
        LDSM4(al, aL);
#pragma unroll
        for (int nt2 = 0; nt2 < 8; nt2++) {
            uint32_t bh[4], bl[4];
            LDSM4(bh, bH + nt2 * 768);
            LDSM4(bl, bL + nt2 * 768);
            mma16816(acc[2 * nt2],     ah, bh[0], bh[2]);
            mma16816(acc[2 * nt2],     ah, bl[0], bl[2]);
            mma16816(acc[2 * nt2],     al, bh[0], bh[2]);
            mma16816(acc[2 * nt2 + 1], ah, bh[1], bh[3]);
            mma16816(acc[2 * nt2 + 1], ah, bl[1], bl[3]);
            mma16816(acc[2 * nt2 + 1], al, bh[1], bh[3]);
        }
        __syncthreads();
    }

    float* po = out + (NSPLIT > 1 ? (long)blockIdx.z * SLICE : 0);
    const int r0 = p0 + m0 + g, r1 = r0 + 8;
    const int b0_ = r0 / HoWo, ri0 = r0 % HoWo;
    const int b1_ = r1 / HoWo, ri1 = r1 % HoWo;
#pragma unroll
    for (int nt = 0; nt < 16; nt++) {
        int co = n0 + nt * 8 + 2 * tg;
        po[((long)(b0_ * COUT + co)) * HoWo + ri0]     = acc[nt][0];
        po[((long)(b0_ * COUT + co + 1)) * HoWo + ri0] = acc[nt][1];
        po[((long)(b1_ * COUT + co)) * HoWo + ri1]     = acc[nt][2];
        po[((long)(b1_ * COUT + co + 1)) * HoWo + ri1] = acc[nt][3];
    }
}

// ---------------- HMMA convt GEMM: 128px x 128m, ldmatrix, dbl-buffer ------
template<int CIN, int COUT, int KS, int H, int W, bool BN, int NSPLIT>
__global__ void __launch_bounds__(256)
tconvt(const float* __restrict__ x, const bf16* __restrict__ wh,
       const bf16* __restrict__ wl,
       const float* __restrict__ scale, const float* __restrict__ shift,
       float* __restrict__ out) {
    constexpr int HW = H * W;
    constexpr int KK = KS * KS;
    constexpr int Hout = H * KS, Wout = W * KS;
    constexpr int Kslice = CIN / NSPLIT;
    constexpr int NCH = Kslice / 16;
    constexpr long SLICE = (long)16 * COUT * Hout * Wout;

    __shared__ __align__(16) bf16 AsH[2][128 * PIT], AsL[2][128 * PIT],
                                  BsH[2][128 * PIT], BsL[2][128 * PIT];

    const int tid = threadIdx.x;
    const int warp = tid >> 5, lane = tid & 31;
    const int g = lane >> 2, tg = lane & 3;
    const int m0 = warp * 16;

    const int p0 = blockIdx.x * 128;
    const int n0 = blockIdx.y * 128;
    const int cbase = blockIdx.z * Kslice;
    const int pb = tid & 127, half = tid >> 7;

    const int aoff = (lane < 16 ? (m0 + lane) * 48 : (m0 + lane - 16) * 48 + 16);
    const int boffl = (lane < 16 ? lane * 48 : (lane - 16) * 48 + 16);
    const uint32_t baseAH0 = (uint32_t)__cvta_generic_to_shared(AsH[0]);
    const uint32_t baseAH1 = (uint32_t)__cvta_generic_to_shared(AsH[1]);
    const uint32_t baseAL0 = (uint32_t)__cvta_generic_to_shared(AsL[0]);
    const uint32_t baseAL1 = (uint32_t)__cvta_generic_to_shared(AsL[1]);
    const uint32_t baseBH0 = (uint32_t)__cvta_generic_to_shared(BsH[0]);
    const uint32_t baseBH1 = (uint32_t)__cvta_generic_to_shared(BsH[1]);
    const uint32_t baseBL0 = (uint32_t)__cvta_generic_to_shared(BsL[0]);
    const uint32_t baseBL1 = (uint32_t)__cvta_generic_to_shared(BsL[1]);

    const int gp = p0 + pb;
    const int bI0 = gp / HW, rI0 = gp % HW;
    const long xrow = (long)bI0 * CIN * HW + rI0;

    auto fill = [&](int c, int buf) {
        {
            int cs = cbase + c * 16 + half * 8;
            uint4 uh, ul;
            bf16* hp = (bf16*)&uh; bf16* lp = (bf16*)&ul;
#pragma unroll
            for (int e = 0; e < 8; e++) {
                int ci = cs + e;
                float v = x[xrow + (long)ci * HW];
                if (BN) {
                    float t = v * scale[ci] + shift[ci];
                    v = fmaxf(t, LEAKK * t);
                }
                bf16 hh = __float2bfloat16(v);
                hp[e] = hh;
                lp[e] = __float2bfloat16(v - __bfloat162float(hh));
            }
            int off = pb * PIT + half * 8;
            *(uint4*)&AsH[buf][off] = uh;
            *(uint4*)&AsL[buf][off] = ul;
        }
        {
            long roff = (long)(n0 + pb) * CIN + cbase + c * 16 + half * 8;
            int off = pb * PIT + half * 8;
            *(uint4*)&BsH[buf][off] = *(const uint4*)(wh + roff);
            *(uint4*)&BsL[buf][off] = *(const uint4*)(wl + roff);
        }
    };

    float acc[16][4];
#pragma unroll
    for (int nt = 0; nt < 16; nt++)
#pragma unroll
        for (int i = 0; i < 4; i++) acc[nt][i] = 0.f;

    fill(0, 0);
    __syncthreads();

    for (int c = 0; c < NCH; c++) {
        int cur = c & 1;
        if (c + 1 < NCH) fill(c + 1, cur ^ 1);
        uint32_t aH = (cur ? baseAH1 : baseAH0) + aoff;
        uint32_t aL = (cur ? baseAL1 : baseAL0) + aoff;
        uint32_t bH = (cur ? baseBH1 : baseBH0) + boffl;
        uint32_t bL = (cur ? baseBL1 : baseBL0) + boffl;
        uint32_t ah[4], al[4];
        LDSM4(ah, aH);
        LDSM4(al, aL);
#pragma unroll
        for (int nt2 = 0; nt2 < 8; nt2++) {
            uint32_t bh[4], bl[4];
            LDSM4(bh, bH + nt2 * 768);
            LDSM4(bl, bL + nt2 * 768);
            mma16816(acc[2 * nt2],     ah, bh[0], bh[2]);
            mma16816(acc[2 * nt2],     ah, bl[0], bl[2]);
            mma16816(acc[2 * nt2],     al, bh[0], bh[2]);
            mma16816(acc[2 * nt2 + 1], ah, bh[1], bh[3]);
            mma16816(acc[2 * nt2 + 1], ah, bl[1], bl[3]);
            mma16816(acc[2 * nt2 + 1], al, bh[1], bh[3]);
        }
        __syncthreads();
    }

    float* po = out + (NSPLIT > 1 ? (long)blockIdx.z * SLICE : 0);
    const int r0 = p0 + m0 + g, r1 = r0 + 8;
    const int b0_ = r0 / HW, ri0 = r0 % HW;
    const int b1_ = r1 / HW, ri1 = r1 % HW;
    const int ih0 = ri0 / W, iw0 = ri0 % W;
    const int ih1 = ri1 / W, iw1 = ri1 % W;
#pragma unroll
    for (int nt = 0; nt < 16; nt++) {
        int n = n0 + nt * 8 + 2 * tg;
#pragma unroll
        for (int l = 0; l < 2; l++) {
            int nn = n + l;
            int co = nn / KK, rem = nn % KK;
            int ki = rem / KS, kj = rem % KS;
            po[((long)(b0_ * COUT + co) * Hout + ih0 * KS + ki) * Wout + iw0 * KS + kj]
                = acc[nt][l];
            po[((long)(b1_ * COUT + co) * Hout + ih1 * KS + ki) * Wout + iw1 * KS + kj]
                = acc[nt][2 + l];
        }
    }
}

// ---------------- K-split combine (nullable bias) ---------------------------
__global__ void combine(const float* __restrict__ part, const float* __restrict__ bias,
                        float* __restrict__ out, int len, int S, int HWo, int CO) {
    int i = blockIdx.x * blockDim.x + threadIdx.x;
    if (i >= len) return;
    float s = 0.f;
    for (int k = 0; k < S; k++) s += part[i + (long)k * len];
    float bv = bias ? bias[(i / HWo) % CO] : 0.f;
    out[i] = s + bv;
}

// ---------------- BN batch stats (two-phase) --------------------------------
__global__ void bnpart(const float* __restrict__ y, int C, int HW,
                       float2* __restrict__ part) {
    int c = blockIdx.x, s = blockIdx.y;
    int seg = HW / 8, r0 = s * seg;
    float sm = 0.f, s2 = 0.f;
    for (int b = 0; b < 16; b++) {
        const float* p = y + (long)(b * C + c) * HW;
        for (int r = r0 + threadIdx.x; r < r0 + seg; r += 256) {
            float v = p[r];
            sm += v; s2 += v * v;
        }
    }
    __shared__ float sh[256], sh2[256];
    sh[threadIdx.x] = sm; sh2[threadIdx.x] = s2;
    __syncthreads();
    for (int o = 128; o > 0; o >>= 1) {
        if (threadIdx.x < o) { sh[threadIdx.x] += sh[threadIdx.x + o];
                               sh2[threadIdx.x] += sh2[threadIdx.x + o]; }
        __syncthreads();
    }
    if (threadIdx.x == 0) part[c * 8 + s] = make_float2(sh[0], sh2[0]);
}

__global__ void bnfin(const float2* __restrict__ part,
                      const float* __restrict__ g, const float* __restrict__ bb,
                      float* __restrict__ scale, float* __restrict__ shift,
                      int C, float invn) {
    int c = threadIdx.x;
    if (c >= C) return;
    float sm = 0.f, s2 = 0.f;
#pragma unroll
    for (int s = 0; s < 8; s++) { float2 p = part[c * 8 + s]; sm += p.x; s2 += p.y; }
    float m = sm * invn;
    float v = s2 * invn - m * m;
    float sc = g[c] * rsqrtf(v + EPSS);
    scale[c] = sc;
    shift[c] = bb[c] - m * sc;
}

// ---------------- codebook squared norms ------------------------------------
__global__ void cnormk(const float* __restrict__ cb, float* __restrict__ cn) {
    int c = blockIdx.x;
    float v = cb[c * 256 + threadIdx.x];
    __shared__ float sh[256];
    sh[threadIdx.x] = v * v;
    __syncthreads();
    for (int o = 128; o > 0; o >>= 1) {
        if (threadIdx.x < o) sh[threadIdx.x] += sh[threadIdx.x + o];
        __syncthreads();
    }
    if (threadIdx.x == 0) cn[c] = sh[0];
}

// ---------------- vector quantizer ------------------------------------------
__global__ void vqk(const float* __restrict__ z, const float* __restrict__ cb,
                    const float* __restrict__ cn, float* __restrict__ q,
                    float* __restrict__ rowloss,
                    float* __restrict__ out_idx, float* __restrict__ out_mind) {
    int row = blockIdx.x;
    int b = row >> 6, hw = row & 63;
    int tid = threadIdx.x, lane = tid & 31, warp = tid >> 5;
    __shared__ float zf[256];
    __shared__ float red[256];

    zf[tid] = z[(b * 256 + tid) * 64 + hw];
    red[tid] = zf[tid] * zf[tid];
    __syncthreads();
    for (int o = 128; o > 0; o >>= 1) {
        if (tid < o) red[tid] += red[tid + o];
        __syncthreads();
    }
    float znorm = red[0];
    __syncthreads();

    float best = 3.4e38f; int bidx = 1 << 20;
    for (int code = warp; code < 512; code += 8) {
        const float* cr = cb + code * 256;
        float dot = 0.f;
#pragma unroll
        for (int k = 0; k < 8; k++) dot += cr[lane + 32 * k] * zf[lane + 32 * k];
#pragma unroll
        for (int o = 16; o > 0; o >>= 1) dot += __shfl_down_sync(0xffffffffu, dot, o);
        if (lane == 0) {
            float d2 = znorm - 2.f * dot + cn[code];
            if (d2 < best || (d2 == best && code < bidx)) { best = d2; bidx = code; }
        }
    }
    __shared__ float wbest[8]; __shared__ int widx[8];
    if (lane == 0) { wbest[warp] = best; widx[warp] = bidx; }
    __syncthreads();
    if (tid == 0) {
        float bb = wbest[0]; int bi = widx[0];
        for (int w = 1; w < 8; w++)
            if (wbest[w] < bb || (wbest[w] == bb && widx[w] < bi)) { bb = wbest[w]; bi = widx[w]; }
        wbest[0] = bb; widx[0] = bi;
    }
    __syncthreads();
    int idx = widx[0];
    float mind = wbest[0];

    float qv = cb[idx * 256 + tid];
    q[(b * 256 + tid) * 64 + hw] = qv;
    float diff = qv - zf[tid];
    red[tid] = diff * diff;
    __syncthreads();
    for (int o = 128; o > 0; o >>= 1) {
        if (tid < o) red[tid] += red[tid + o];
        __syncthreads();
    }
    if (tid == 0) {
        rowloss[row] = red[0];
        out_idx[row] = (float)idx;
        out_mind[row] = mind;
    }
}

__global__ void lossfin(const float* __restrict__ rowloss, float* __restrict__ out) {
    __shared__ float sh[256];
    float s = 0.f;
    for (int i = threadIdx.x; i < 1024; i += 256) s += rowloss[i];
    sh[threadIdx.x] = s; __syncthreads();
    for (int o = 128; o > 0; o >>= 1) {
        if (threadIdx.x < o) sh[threadIdx.x] += sh[threadIdx.x + o];
        __syncthreads();
    }
    if (threadIdx.x == 0) {
        float L = sh[0] / (1024.f * 256.f);
        out[786432] = L;
        out[786433] = L;
    }
}

// ---------------- final 1x1 conv + tanh -------------------------------------
__global__ void final1x1(const float* __restrict__ h, const float* __restrict__ w3,
                         const float* __restrict__ b3,
                         const float* __restrict__ scale, const float* __restrict__ shift,
                         float* __restrict__ out) {
    __shared__ float sw[96], ssc[32], ssh[32], sb[3];
    if (threadIdx.x < 96) sw[threadIdx.x] = w3[threadIdx.x];
    if (threadIdx.x < 32) { ssc[threadIdx.x] = scale[threadIdx.x];
                            ssh[threadIdx.x] = shift[threadIdx.x]; }
    if (threadIdx.x < 3) sb[threadIdx.x] = b3[threadIdx.x];
    __syncthreads();
    const int HW = 128 * 128;
    int gid = blockIdx.x * blockDim.x + threadIdx.x;
    int b = gid / HW, r = gid % HW;
    float a0 = 0.f, a1 = 0.f, a2 = 0.f;
#pragma unroll 8
    for (int c = 0; c < 32; c++) {
        float v = h[(b * 32 + c) * HW + r];
        v = v * ssc[c] + ssh[c];
        v = fmaxf(v, LEAKK * v);
        a0 += v * sw[c];
        a1 += v * sw[32 + c];
        a2 += v * sw[64 + c];
    }
    out[(b * 3 + 0) * HW + r] = tanhf(a0 + sb[0]);
    out[(b * 3 + 1) * HW + r] = tanhf(a1 + sb[1]);
    out[(b * 3 + 2) * HW + r] = tanhf(a2 + sb[2]);
}

// ----------------------------------------------------------------------------
extern "C" void kernel_launch(void* const* d_in, const int* in_sizes, int n_in,
                              void* d_out, int out_size) {
    (void)n_in; (void)out_size;

    const float* x = (const float*)d_in[0];
    const float *ew0, *eb0, *eg0, *ebb0;
    const float *ew1, *eg1, *ebb1;
    const float *ew2, *eg2, *ebb2;
    const float *ew3, *eb3;

    if (in_sizes[3] == 64) {
        ew0 = (const float*)d_in[1];  eb0 = (const float*)d_in[2];
        eg0 = (const float*)d_in[3];  ebb0 = (const float*)d_in[4];
        ew1 = (const float*)d_in[5];
        eg1 = (const float*)d_in[7];  ebb1 = (const float*)d_in[8];
        ew2 = (const float*)d_in[9];
        eg2 = (const float*)d_in[11]; ebb2 = (const float*)d_in[12];
        ew3 = (const float*)d_in[13]; eb3 = (const float*)d_in[14];
    } else {
        ew0 = (const float*)d_in[1];  eb0 = (const float*)d_in[2];
        ew1 = (const float*)d_in[3];
        ew2 = (const float*)d_in[5];
        ew3 = (const float*)d_in[7];  eb3 = (const float*)d_in[8];
        eg0 = (const float*)d_in[9];  ebb0 = (const float*)d_in[10];
        eg1 = (const float*)d_in[11]; ebb1 = (const float*)d_in[12];
        eg2 = (const float*)d_in[13]; ebb2 = (const float*)d_in[14];
    }

    const float* cb   = (const float*)d_in[15];
    const float* dw0  = (const float*)d_in[16];
    const float* dg0  = (const float*)d_in[18];
    const float* dbb0 = (const float*)d_in[19];
    const float* dw1  = (const float*)d_in[20];
    const float* dg1  = (const float*)d_in[22];
    const float* dbb1 = (const float*)d_in[23];
    const float* dw2  = (const float*)d_in[24];
    const float* dg2  = (const float*)d_in[26];
    const float* dbb2 = (const float*)d_in[27];
    const float* dw3  = (const float*)d_in[28];
    const float* db3  = (const float*)d_in[29];
    float* out = (float*)d_out;

    float *y0, *y1, *y2, *z, *q, *d0, *d1, *d2, *wt, *part, *sc, *sf, *cn, *rl;
    bf16 *wbh, *wbl;
    float2* bnp;
    cudaGetSymbolAddress((void**)&y0, g_y0);
    cudaGetSymbolAddress((void**)&y1, g_y1);
    cudaGetSymbolAddress((void**)&y2, g_y2);
    cudaGetSymbolAddress((void**)&z,  g_z);
    cudaGetSymbolAddress((void**)&q,  g_q);
    cudaGetSymbolAddress((void**)&d0, g_d0);
    cudaGetSymbolAddress((void**)&d1, g_d1);
    cudaGetSymbolAddress((void**)&d2, g_d2);
    cudaGetSymbolAddress((void**)&wt, g_wt);
    cudaGetSymbolAddress((void**)&part, g_part);
    cudaGetSymbolAddress((void**)&wbh, g_wbh);
    cudaGetSymbolAddress((void**)&wbl, g_wbl);
    cudaGetSymbolAddress((void**)&sc, g_scale);
    cudaGetSymbolAddress((void**)&sf, g_shift);
    cudaGetSymbolAddress((void**)&cn, g_cnorm);
    cudaGetSymbolAddress((void**)&rl, g_rowloss);
    cudaGetSymbolAddress((void**)&bnp, g_bnp);

    const long OF_E1 = 0, OF_E2 = 131072, OF_E3 = 655360;
    const long OF_D0 = 1703936, OF_D1 = 2228224, OF_D2 = 2260992;

    dim3 t32(32, 8);
    wtrans<<<dim3(2, 2), t32>>>(ew0, wt, 64, 48);
    wsplit<<<512,  256>>>(ew1, wbh + OF_E1, wbl + OF_E1, 131072);
    wsplit<<<2048, 256>>>(ew2, wbh + OF_E2, wbl + OF_E2, 524288);
    wsplit<<<4096, 256>>>(ew3, wbh + OF_E3, wbl + OF_E3, 1048576);
    wsplit_t<<<dim3(64, 8), t32>>>(dw0, wbh + OF_D0, wbl + OF_D0, 256, 2048);
    wsplit_t<<<dim3(8, 4),  t32>>>(dw1, wbh + OF_D1, wbl + OF_D1, 128, 256);
    wsplit_t<<<dim3(4, 2),  t32>>>(dw2, wbh + OF_D2, wbl + OF_D2, 64, 128);
    cnormk<<<512, 256>>>(cb, cn);

    // ---- encoder ----
    gconv<3, 64, 128, 128><<<dim3(1024, 1), 256>>>(x, wt, eb0, y0);
    bnpart<<<dim3(64, 8), 256>>>(y0, 64, 4096, bnp);
    bnfin<<<1, 64>>>(bnp, eg0, ebb0, sc + 0*256, sf + 0*256, 64, 1.f/(16.f*4096.f));

    tconv<64, 128, 64, 64, true, 2><<<dim3(128, 1, 2), 256>>>(y0, wbh + OF_E1, wbl + OF_E1, sc + 0*256, sf + 0*256, part);
    combine<<<8192, 256>>>(part, nullptr, y1, 2097152, 2, 1024, 128);
    bnpart<<<dim3(128, 8), 256>>>(y1, 128, 1024, bnp);
    bnfin<<<1, 128>>>(bnp, eg1, ebb1, sc + 1*256, sf + 1*256, 128, 1.f/(16.f*1024.f));

    tconv<128, 256, 32, 32, true, 4><<<dim3(32, 2, 4), 256>>>(y1, wbh + OF_E2, wbl + OF_E2, sc + 1*256, sf + 1*256, part);
    combine<<<4096, 256>>>(part, nullptr, y2, 1048576, 4, 256, 256);
    bnpart<<<dim3(256, 8), 256>>>(y2, 256, 256, bnp);
    bnfin<<<1, 256>>>(bnp, eg2, ebb2, sc + 2*256, sf + 2*256, 256, 1.f/(16.f*256.f));

    tconv<256, 256, 16, 16, true, 16><<<dim3(8, 2, 16), 256>>>(y2, wbh + OF_E3, wbl + OF_E3, sc + 2*256, sf + 2*256, part);
    combine<<<1024, 256>>>(part, eb3, z, 262144, 16, 64, 256);

    // ---- vector quantizer ----
    vqk<<<1024, 256>>>(z, cb, cn, q, rl, out + 786434, out + 786434 + 1024);
    lossfin<<<1, 256>>>(rl, out);

    // ---- decoder ----
    tconvt<256, 128, 4, 8, 8, false, 2><<<dim3(8, 16, 2), 256>>>(q, wbh + OF_D0, wbl + OF_D0, nullptr, nullptr, part);
    combine<<<8192, 256>>>(part, nullptr, d0, 2097152, 2, 1024, 128);
    bnpart<<<dim3(128, 8), 256>>>(d0, 128, 1024, bnp);
    bnfin<<<1, 128>>>(bnp, dg0, dbb0, sc + 3*256, sf + 3*256, 128, 1.f/(16.f*1024.f));

    tconvt<128, 64, 2, 32, 32, true, 1><<<dim3(128, 2, 1), 256>>>(d0, wbh + OF_D1, wbl + OF_D1, sc + 3*256, sf + 3*256, d1);
    bnpart<<<dim3(64, 8), 256>>>(d1, 64, 4096, bnp);
    bnfin<<<1, 64>>>(bnp, dg1, dbb1, sc + 4*256, sf + 4*256, 64, 1.f/(16.f*4096.f));

    tconvt<64, 32, 2, 64, 64, true, 1><<<dim3(512, 1, 1), 256>>>(d1, wbh + OF_D2, wbl + OF_D2, sc + 4*256, sf + 4*256, d2);
    bnpart<<<dim3(32, 8), 256>>>(d2, 32, 16384, bnp);
    bnfin<<<1, 32>>>(bnp, dg2, dbb2, sc + 5*256, sf + 5*256, 32, 1.f/(16.f*16384.f));

    final1x1<<<1024, 256>>>(d2, dw3, db3, sc + 5*256, sf + 5*256, out);
}

// round 17
// speedup vs baseline: 1.4952x; 1.1246x over previous
#include <cuda_runtime.h>
#include <cuda_bf16.h>
#include <math.h>
#include <stdint.h>

#define LEAKK 0.01f
#define EPSS  1e-5f

typedef __nv_bfloat16 bf16;

// packed fp32x2 FMA — enc0 kernel only
#define FMA2(acc, a, b) \
    asm("fma.rn.f32x2 %0, %1, %2, %0;" : "+l"(acc) : "l"(a), "l"(b))

__device__ __forceinline__ float2 unpk(unsigned long long p) {
    unsigned int lo, hi;
    asm("mov.b64 {%0,%1}, %2;" : "=r"(lo), "=r"(hi) : "l"(p));
    return make_float2(__uint_as_float(lo), __uint_as_float(hi));
}

// mma.sync m16n8k16 row.col bf16 -> f32
__device__ __forceinline__ void mma16816(float* d, const uint32_t* a,
                                         uint32_t b0, uint32_t b1) {
    asm volatile(
        "mma.sync.aligned.m16n8k16.row.col.f32.bf16.bf16.f32 "
        "{%0,%1,%2,%3}, {%4,%5,%6,%7}, {%8,%9}, {%0,%1,%2,%3};"
        : "+f"(d[0]), "+f"(d[1]), "+f"(d[2]), "+f"(d[3])
        : "r"(a[0]), "r"(a[1]), "r"(a[2]), "r"(a[3]), "r"(b0), "r"(b1));
}

// ldmatrix x4 (b16, no trans)
#define LDSM4(r, addr) \
    asm volatile("ldmatrix.sync.aligned.m8n8.x4.shared.b16 {%0,%1,%2,%3}, [%4];" \
        : "=r"((r)[0]), "=r"((r)[1]), "=r"((r)[2]), "=r"((r)[3]) : "r"(addr))

// ---------------- scratch (device globals; no allocation) ----------------
__device__ float g_y0[16*64*64*64];
__device__ float g_y1[16*128*32*32];
__device__ float g_y2[16*256*16*16];
__device__ float g_z [16*256*8*8];
__device__ float g_q [16*256*8*8];
__device__ float g_d0[16*128*32*32];
__device__ float g_d1[16*64*64*64];
__device__ float g_d2[16*32*128*128];
__device__ float g_wt[4096];
__device__ float g_part[4194304];
__device__ bf16  g_wbh[2269184];
__device__ bf16  g_wbl[2269184];
__device__ float g_scale[6*256];
__device__ float g_shift[6*256];
__device__ float g_cnorm[512];
__device__ float g_rowloss[1024];
__device__ float2 g_bnp[256*8];

// ---------------- smem-tiled transpose (enc0 weights) ---------------------
__global__ void wtrans(const float* __restrict__ in, float* __restrict__ outp,
                       int R, int Ccol) {
    __shared__ float t[32][33];
    int bx = blockIdx.x * 32, by = blockIdx.y * 32;
    int tx = threadIdx.x, ty = threadIdx.y;
#pragma unroll
    for (int j = 0; j < 4; j++) {
        int xx = bx + tx, yy = by + ty + j * 8;
        if (xx < Ccol && yy < R) t[ty + j * 8][tx] = in[yy * Ccol + xx];
    }
    __syncthreads();
#pragma unroll
    for (int j = 0; j < 4; j++) {
        int xx = by + tx, yy = bx + ty + j * 8;
        if (xx < R && yy < Ccol) outp[yy * R + xx] = t[tx][ty + j * 8];
    }
}

// ---------------- weight split: fp32 -> bf16 hi/lo -------------------------
__global__ void wsplit(const float* __restrict__ w, bf16* __restrict__ h,
                       bf16* __restrict__ l, int n) {
    int i = blockIdx.x * blockDim.x + threadIdx.x;
    if (i >= n) return;
    float v = w[i];
    bf16 hh = __float2bfloat16(v);
    h[i] = hh;
    l[i] = __float2bfloat16(v - __bfloat162float(hh));
}

// ---------------- transpose + split: in[R][C] -> h/l [C][R] ----------------
__global__ void wsplit_t(const float* __restrict__ in, bf16* __restrict__ oh,
                         bf16* __restrict__ ol, int R, int C) {
    __shared__ float t[32][33];
    int bx = blockIdx.x * 32, by = blockIdx.y * 32;
    int tx = threadIdx.x, ty = threadIdx.y;
#pragma unroll
    for (int j = 0; j < 4; j++) {
        int xx = bx + tx, yy = by + ty + j * 8;
        if (xx < C && yy < R) t[ty + j * 8][tx] = in[yy * C + xx];
    }
    __syncthreads();
#pragma unroll
    for (int j = 0; j < 4; j++) {
        int cc = bx + ty + j * 8, rr = by + tx;
        if (cc < C && rr < R) {
            float v = t[tx][ty + j * 8];
            bf16 hh = __float2bfloat16(v);
            oh[cc * R + rr] = hh;
            ol[cc * R + rr] = __float2bfloat16(v - __bfloat162float(hh));
        }
    }
}

// ---------------- enc0 conv (FMA2 64x64 tile, proven) ----------------------
template<int CIN, int COUT, int H, int W>
__global__ void __launch_bounds__(256)
gconv(const float* __restrict__ x, const float* __restrict__ wt,
      const float* __restrict__ bias, float* __restrict__ out) {
    constexpr int Ho = H / 2, Wo = W / 2, HoWo = Ho * Wo;
    __shared__ float Asd[2][16][128];
    __shared__ float Bs [2][16][64];
    const int tid = threadIdx.x;
    const int tx = tid & 15, ty = tid >> 4;
    const int p0 = blockIdx.x * 64, co0 = blockIdx.y * 64;
    const int pp = tid & 63, cc = tid & 63;
    int kkj[4], boff[4]; bool val[4];
    {
        int gp = p0 + pp;
        int b = gp / HoWo, r = gp % HoWo;
        int oh = r / Wo, ow = r % Wo;
#pragma unroll
        for (int j = 0; j < 4; j++) {
            int kk = (tid >> 6) + 4 * j;
            int kh = kk >> 2, kw = kk & 3;
            int ih = 2 * oh - 1 + kh, iw = 2 * ow - 1 + kw;
            val[j] = (ih >= 0) && (ih < H) && (iw >= 0) && (iw < W);
            kkj[j] = kk;
            boff[j] = (b * CIN) * H * W + ih * W + iw;
        }
    }
    float bv[4], av[4];
    auto gather = [&](int ci) {
#pragma unroll
        for (int j = 0; j < 4; j++) {
            float v = 0.f;
            if (val[j]) v = x[boff[j] + ci * (H * W)];
            bv[j] = v;
            av[j] = wt[(ci * 16 + kkj[j]) * COUT + co0 + cc];
        }
    };
    auto stobuf = [&](int nb) {
#pragma unroll
        for (int j = 0; j < 4; j++) {
            Bs[nb][kkj[j]][pp] = bv[j];
            *(float2*)&Asd[nb][kkj[j]][2 * cc] = make_float2(av[j], av[j]);
        }
    };
    gather(0); stobuf(0);
    __syncthreads();
    unsigned long long acc[4][2];
#pragma unroll
    for (int i = 0; i < 4; i++) { acc[i][0] = 0ULL; acc[i][1] = 0ULL; }
    for (int c = 0; c < CIN; c++) {
        int cur = c & 1;
        bool more = (c + 1) < CIN;
        if (more) gather(c + 1);
#pragma unroll
        for (int k = 0; k < 16; k++) {
            ulonglong2 b2  = *(const ulonglong2*)&Bs [cur][k][4 * tx];
            ulonglong2 a01 = *(const ulonglong2*)&Asd[cur][k][8 * ty];
            ulonglong2 a23 = *(const ulonglong2*)&Asd[cur][k][8 * ty + 4];
            FMA2(acc[0][0], a01.x, b2.x); FMA2(acc[0][1], a01.x, b2.y);
            FMA2(acc[1][0], a01.y, b2.x); FMA2(acc[1][1], a01.y, b2.y);
            FMA2(acc[2][0], a23.x, b2.x); FMA2(acc[2][1], a23.x, b2.y);
            FMA2(acc[3][0], a23.y, b2.x); FMA2(acc[3][1], a23.y, b2.y);
        }
        if (more) stobuf(cur ^ 1);
        __syncthreads();
    }
    const int b = p0 / HoWo;
    const int rb = (p0 % HoWo) + 4 * tx;
#pragma unroll
    for (int i = 0; i < 4; i++) {
        int co = co0 + 4 * ty + i;
        float bvs = bias[co];
        float2 u0 = unpk(acc[i][0]);
        float2 u1 = unpk(acc[i][1]);
        *(float4*)&out[(b * COUT + co) * HoWo + rb]
            = make_float4(u0.x + bvs, u0.y + bvs, u1.x + bvs, u1.y + bvs);
    }
}

// PITCH: 24 bf16 (48B) rows — conflict-free for ldmatrix phases
#define PIT 24

// ---------------- HMMA conv GEMM: ldmatrix + reg-prefetch pipeline ---------
template<int CIN, int COUT, int H, int W, bool BN, int NSPLIT>
__global__ void __launch_bounds__(256)
tconv(const float* __restrict__ x, const bf16* __restrict__ wh,
      const bf16* __restrict__ wl,
      const float* __restrict__ scale, const float* __restrict__ shift,
      float* __restrict__ out) {
    constexpr int Ho = H / 2, Wo = W / 2, HoWo = Ho * Wo;
    constexpr int Kfull = CIN * 16;
    constexpr int Kslice = Kfull / NSPLIT;
    constexpr int NCH = Kslice / 16;
    constexpr long SLICE = (long)16 * HoWo * COUT;

    __shared__ __align__(16) bf16 AsH[2][128 * PIT], AsL[2][128 * PIT],
                                  BsH[2][128 * PIT], BsL[2][128 * PIT];

    const int tid = threadIdx.x;
    const int warp = tid >> 5, lane = tid & 31;
    const int g = lane >> 2, tg = lane & 3;
    const int m0 = warp * 16;

    const int p0 = blockIdx.x * 128;
    const int n0 = blockIdx.y * 128;
    const int k0 = blockIdx.z * Kslice;
    const int pb = tid & 127, half = tid >> 7;

    const int aoff = (lane < 16 ? (m0 + lane) * 48 : (m0 + lane - 16) * 48 + 16);
    const int boffl = (lane < 16 ? lane * 48 : (lane - 16) * 48 + 16);
    const uint32_t baseAH0 = (uint32_t)__cvta_generic_to_shared(AsH[0]);
    const uint32_t baseAH1 = (uint32_t)__cvta_generic_to_shared(AsH[1]);
    const uint32_t baseAL0 = (uint32_t)__cvta_generic_to_shared(AsL[0]);
    const uint32_t baseAL1 = (uint32_t)__cvta_generic_to_shared(AsL[1]);
    const uint32_t baseBH0 = (uint32_t)__cvta_generic_to_shared(BsH[0]);
    const uint32_t baseBH1 = (uint32_t)__cvta_generic_to_shared(BsH[1]);
    const uint32_t baseBL0 = (uint32_t)__cvta_generic_to_shared(BsL[0]);
    const uint32_t baseBL1 = (uint32_t)__cvta_generic_to_shared(BsL[1]);

    int boffs[8]; unsigned vm = 0;
    {
        int gp = p0 + pb;
        int b = gp / HoWo, r = gp % HoWo;
        int oh = r / Wo, ow = r % Wo;
        int ih0 = 2 * oh - 1, iw0 = 2 * ow - 1;
        int xbase = b * CIN * H * W;
#pragma unroll
        for (int e = 0; e < 8; e++) {
            int kk = half * 8 + e;
            int kh = kk >> 2, kw = kk & 3;
            int ih = ih0 + kh, iw = iw0 + kw;
            if (ih >= 0 && ih < H && iw >= 0 && iw < W) vm |= (1u << e);
            boffs[e] = xbase + ih * W + iw;
        }
    }

    float avr[8]; uint4 b4h, b4l;
    auto load_g = [&](int c) {                  // LDG only, no use
        int ci = (k0 + c * 16) >> 4;
        const float* xch = x + (long)ci * (H * W);
#pragma unroll
        for (int e = 0; e < 8; e++)
            avr[e] = ((vm >> e) & 1) ? xch[boffs[e]] : 0.f;
        long roff = (long)(n0 + pb) * Kfull + k0 + c * 16 + half * 8;
        b4h = *(const uint4*)(wh + roff);
        b4l = *(const uint4*)(wl + roff);
    };
    auto cvt_store = [&](int c, int buf) {      // split + STS
        int ci = (k0 + c * 16) >> 4;
        float sc_ = 1.f, sf_ = 0.f;
        if (BN) { sc_ = scale[ci]; sf_ = shift[ci]; }
        uint4 uh, ul;
        bf16* hp = (bf16*)&uh; bf16* lp = (bf16*)&ul;
#pragma unroll
        for (int e = 0; e < 8; e++) {
            float v = avr[e];
            if (BN && ((vm >> e) & 1)) {
                v = v * sc_ + sf_; v = fmaxf(v, LEAKK * v);
            }
            bf16 hh = __float2bfloat16(v);
            hp[e] = hh;
            lp[e] = __float2bfloat16(v - __bfloat162float(hh));
        }
        int off = pb * PIT + half * 8;
        *(uint4*)&AsH[buf][off] = uh;
        *(uint4*)&AsL[buf][off] = ul;
        *(uint4*)&BsH[buf][off] = b4h;
        *(uint4*)&BsL[buf][off] = b4l;
    };

    float acc[16][4];
#pragma unroll
    for (int nt = 0; nt < 16; nt++)
#pragma unroll
        for (int i = 0; i < 4; i++) acc[nt][i] = 0.f;

    load_g(0);
    cvt_store(0, 0);
    __syncthreads();

    for (int c = 0; c < NCH; c++) {
        int cur = c & 1;
        bool more = (c + 1) < NCH;
        if (more) load_g(c + 1);
        uint32_t aH = (cur ? baseAH1 : baseAH0) + aoff;
        uint32_t aL = (cur ? baseAL1 : baseAL0) + aoff;
        uint32_t bH = (cur ? baseBH1 : baseBH0) + boffl;
        uint32_t bL = (cur ? baseBL1 : baseBL0) + boffl;
        uint32_t ah[4], al[4];
        LDSM4(ah, aH);
        LDSM4(al, aL);
#pragma unroll
        for (int nt2 = 0; nt2 < 8; nt2++) {
            uint32_t bh[4], bl[4];
            LDSM4(bh, bH + nt2 * 768);
            LDSM4(bl, bL + nt2 * 768);
            mma16816(acc[2 * nt2],     ah, bh[0], bh[2]);
            mma16816(acc[2 * nt2],     ah, bl[0], bl[2]);
            mma16816(acc[2 * nt2],     al, bh[0], bh[2]);
            mma16816(acc[2 * nt2 + 1], ah, bh[1], bh[3]);
            mma16816(acc[2 * nt2 + 1], ah, bl[1], bl[3]);
            mma16816(acc[2 * nt2 + 1], al, bh[1], bh[3]);
        }
        if (more) cvt_store(c + 1, cur ^ 1);
        __syncthreads();
    }

    float* po = out + (NSPLIT > 1 ? (long)blockIdx.z * SLICE : 0);
    const int r0 = p0 + m0 + g, r1 = r0 + 8;
    const int b0_ = r0 / HoWo, ri0 = r0 % HoWo;
    const int b1_ = r1 / HoWo, ri1 = r1 % HoWo;
#pragma unroll
    for (int nt = 0; nt < 16; nt++) {
        int co = n0 + nt * 8 + 2 * tg;
        po[((long)(b0_ * COUT + co)) * HoWo + ri0]     = acc[nt][0];
        po[((long)(b0_ * COUT + co + 1)) * HoWo + ri0] = acc[nt][1];
        po[((long)(b1_ * COUT + co)) * HoWo + ri1]     = acc[nt][2];
        po[((long)(b1_ * COUT + co + 1)) * HoWo + ri1] = acc[nt][3];
    }
}

// ---------------- HMMA convt GEMM: ldmatrix + reg-prefetch pipeline --------
template<int CIN, int COUT, int KS, int H, int W, bool BN, int NSPLIT>
__global__ void __launch_bounds__(256)
tconvt(const float* __restrict__ x, const bf16* __restrict__ wh,
       const bf16* __restrict__ wl,
       const float* __restrict__ scale, const float* __restrict__ shift,
       float* __restrict__ out) {
    constexpr int HW = H * W;
    constexpr int KK = KS * KS;
    constexpr int Hout = H * KS, Wout = W * KS;
    constexpr int Kslice = CIN / NSPLIT;
    constexpr int NCH = Kslice / 16;
    constexpr long SLICE = (long)16 * COUT * Hout * Wout;

    __shared__ __align__(16) bf16 AsH[2][128 * PIT], AsL[2][128 * PIT],
                                  BsH[2][128 * PIT], BsL[2][128 * PIT];

    const int tid = threadIdx.x;
    const int warp = tid >> 5, lane = tid & 31;
    const int g = lane >> 2, tg = lane & 3;
    const int m0 = warp * 16;

    const int p0 = blockIdx.x * 128;
    const int n0 = blockIdx.y * 128;
    const int cbase = blockIdx.z * Kslice;
    const int pb = tid & 127, half = tid >> 7;

    const int aoff = (lane < 16 ? (m0 + lane) * 48 : (m0 + lane - 16) * 48 + 16);
    const int boffl = (lane < 16 ? lane * 48 : (lane - 16) * 48 + 16);
    const uint32_t baseAH0 = (uint32_t)__cvta_generic_to_shared(AsH[0]);
    const uint32_t baseAH1 = (uint32_t)__cvta_generic_to_shared(AsH[1]);
    const uint32_t baseAL0 = (uint32_t)__cvta_generic_to_shared(AsL[0]);
    const uint32_t baseAL1 = (uint32_t)__cvta_generic_to_shared(AsL[1]);
    const uint32_t baseBH0 = (uint32_t)__cvta_generic_to_shared(BsH[0]);
    const uint32_t baseBH1 = (uint32_t)__cvta_generic_to_shared(BsH[1]);
    const uint32_t baseBL0 = (uint32_t)__cvta_generic_to_shared(BsL[0]);
    const uint32_t baseBL1 = (uint32_t)__cvta_generic_to_shared(BsL[1]);

    const int gp = p0 + pb;
    const int bI0 = gp / HW, rI0 = gp % HW;
    const long xrow = (long)bI0 * CIN * HW + rI0;

    float avr[8]; uint4 b4h, b4l;
    auto load_g = [&](int c) {
        int cs = cbase + c * 16 + half * 8;
#pragma unroll
        for (int e = 0; e < 8; e++)
            avr[e] = x[xrow + (long)(cs + e) * HW];
        long roff = (long)(n0 + pb) * CIN + cbase + c * 16 + half * 8;
        b4h = *(const uint4*)(wh + roff);
        b4l = *(const uint4*)(wl + roff);
    };
    auto cvt_store = [&](int c, int buf) {
        int cs = cbase + c * 16 + half * 8;
        uint4 uh, ul;
        bf16* hp = (bf16*)&uh; bf16* lp = (bf16*)&ul;
#pragma unroll
        for (int e = 0; e < 8; e++) {
            float v = avr[e];
            if (BN) {
                int ci = cs + e;
                float t = v * scale[ci] + shift[ci];
                v = fmaxf(t, LEAKK * t);
            }
            bf16 hh = __float2bfloat16(v);
            hp[e] = hh;
            lp[e] = __float2bfloat16(v - __bfloat162float(hh));
        }
        int off = pb * PIT + half * 8;
        *(uint4*)&AsH[buf][off] = uh;
        *(uint4*)&AsL[buf][off] = ul;
        *(uint4*)&BsH[buf][off] = b4h;
        *(uint4*)&BsL[buf][off] = b4l;
    };

    float acc[16][4];
#pragma unroll
    for (int nt = 0; nt < 16; nt++)
#pragma unroll
        for (int i = 0; i < 4; i++) acc[nt][i] = 0.f;

    load_g(0);
    cvt_store(0, 0);
    __syncthreads();

    for (int c = 0; c < NCH; c++) {
        int cur = c & 1;
        bool more = (c + 1) < NCH;
        if (more) load_g(c + 1);
        uint32_t aH = (cur ? baseAH1 : baseAH0) + aoff;
        uint32_t aL = (cur ? baseAL1 : baseAL0) + aoff;
        uint32_t bH = (cur ? baseBH1 : baseBH0) + boffl;
        uint32_t bL = (cur ? baseBL1 : baseBL0) + boffl;
        uint32_t ah[4], al[4];
        LDSM4(ah, aH);
        LDSM4(al, aL);
#pragma unroll
        for (int nt2 = 0; nt2 < 8; nt2++) {
            uint32_t bh[4], bl[4];
            LDSM4(bh, bH + nt2 * 768);
            LDSM4(bl, bL + nt2 * 768);
            mma16816(acc[2 * nt2],     ah, bh[0], bh[2]);
            mma16816(acc[2 * nt2],     ah, bl[0], bl[2]);
            mma16816(acc[2 * nt2],     al, bh[0], bh[2]);
            mma16816(acc[2 * nt2 + 1], ah, bh[1], bh[3]);
            mma16816(acc[2 * nt2 + 1], ah, bl[1], bl[3]);
            mma16816(acc[2 * nt2 + 1], al, bh[1], bh[3]);
        }
        if (more) cvt_store(c + 1, cur ^ 1);
        __syncthreads();
    }

    float* po = out + (NSPLIT > 1 ? (long)blockIdx.z * SLICE : 0);
    const int r0 = p0 + m0 + g, r1 = r0 + 8;
    const int b0_ = r0 / HW, ri0 = r0 % HW;
    const int b1_ = r1 / HW, ri1 = r1 % HW;
    const int ih0 = ri0 / W, iw0 = ri0 % W;
    const int ih1 = ri1 / W, iw1 = ri1 % W;
#pragma unroll
    for (int nt = 0; nt < 16; nt++) {
        int n = n0 + nt * 8 + 2 * tg;
#pragma unroll
        for (int l = 0; l < 2; l++) {
            int nn = n + l;
            int co = nn / KK, rem = nn % KK;
            int ki = rem / KS, kj = rem % KS;
            po[((long)(b0_ * COUT + co) * Hout + ih0 * KS + ki) * Wout + iw0 * KS + kj]
                = acc[nt][l];
            po[((long)(b1_ * COUT + co) * Hout + ih1 * KS + ki) * Wout + iw1 * KS + kj]
                = acc[nt][2 + l];
        }
    }
}

// ---------------- K-split combine (nullable bias) ---------------------------
__global__ void combine(const float* __restrict__ part, const float* __restrict__ bias,
                        float* __restrict__ out, int len, int S, int HWo, int CO) {
    int i = blockIdx.x * blockDim.x + threadIdx.x;
    if (i >= len) return;
    float s = 0.f;
    for (int k = 0; k < S; k++) s += part[i + (long)k * len];
    float bv = bias ? bias[(i / HWo) % CO] : 0.f;
    out[i] = s + bv;
}

// ---------------- BN batch stats (two-phase) --------------------------------
__global__ void bnpart(const float* __restrict__ y, int C, int HW,
                       float2* __restrict__ part) {
    int c = blockIdx.x, s = blockIdx.y;
    int seg = HW / 8, r0 = s * seg;
    float sm = 0.f, s2 = 0.f;
    for (int b = 0; b < 16; b++) {
        const float* p = y + (long)(b * C + c) * HW;
        for (int r = r0 + threadIdx.x; r < r0 + seg; r += 256) {
            float v = p[r];
            sm += v; s2 += v * v;
        }
    }
    __shared__ float sh[256], sh2[256];
    sh[threadIdx.x] = sm; sh2[threadIdx.x] = s2;
    __syncthreads();
    for (int o = 128; o > 0; o >>= 1) {
        if (threadIdx.x < o) { sh[threadIdx.x] += sh[threadIdx.x + o];
                               sh2[threadIdx.x] += sh2[threadIdx.x + o]; }
        __syncthreads();
    }
    if (threadIdx.x == 0) part[c * 8 + s] = make_float2(sh[0], sh2[0]);
}

__global__ void bnfin(const float2* __restrict__ part,
                      const float* __restrict__ g, const float* __restrict__ bb,
                      float* __restrict__ scale, float* __restrict__ shift,
                      int C, float invn) {
    int c = threadIdx.x;
    if (c >= C) return;
    float sm = 0.f, s2 = 0.f;
#pragma unroll
    for (int s = 0; s < 8; s++) { float2 p = part[c * 8 + s]; sm += p.x; s2 += p.y; }
    float m = sm * invn;
    float v = s2 * invn - m * m;
    float sc = g[c] * rsqrtf(v + EPSS);
    scale[c] = sc;
    shift[c] = bb[c] - m * sc;
}

// ---------------- codebook squared norms ------------------------------------
__global__ void cnormk(const float* __restrict__ cb, float* __restrict__ cn) {
    int c = blockIdx.x;
    float v = cb[c * 256 + threadIdx.x];
    __shared__ float sh[256];
    sh[threadIdx.x] = v * v;
    __syncthreads();
    for (int o = 128; o > 0; o >>= 1) {
        if (threadIdx.x < o) sh[threadIdx.x] += sh[threadIdx.x + o];
        __syncthreads();
    }
    if (threadIdx.x == 0) cn[c] = sh[0];
}

// ---------------- vector quantizer ------------------------------------------
__global__ void vqk(const float* __restrict__ z, const float* __restrict__ cb,
                    const float* __restrict__ cn, float* __restrict__ q,
                    float* __restrict__ rowloss,
                    float* __restrict__ out_idx, float* __restrict__ out_mind) {
    int row = blockIdx.x;
    int b = row >> 6, hw = row & 63;
    int tid = threadIdx.x, lane = tid & 31, warp = tid >> 5;
    __shared__ float zf[256];
    __shared__ float red[256];

    zf[tid] = z[(b * 256 + tid) * 64 + hw];
    red[tid] = zf[tid] * zf[tid];
    __syncthreads();
    for (int o = 128; o > 0; o >>= 1) {
        if (tid < o) red[tid] += red[tid + o];
        __syncthreads();
    }
    float znorm = red[0];
    __syncthreads();

    float best = 3.4e38f; int bidx = 1 << 20;
    for (int code = warp; code < 512; code += 8) {
        const float* cr = cb + code * 256;
        float dot = 0.f;
#pragma unroll
        for (int k = 0; k < 8; k++) dot += cr[lane + 32 * k] * zf[lane + 32 * k];
#pragma unroll
        for (int o = 16; o > 0; o >>= 1) dot += __shfl_down_sync(0xffffffffu, dot, o);
        if (lane == 0) {
            float d2 = znorm - 2.f * dot + cn[code];
            if (d2 < best || (d2 == best && code < bidx)) { best = d2; bidx = code; }
        }
    }
    __shared__ float wbest[8]; __shared__ int widx[8];
    if (lane == 0) { wbest[warp] = best; widx[warp] = bidx; }
    __syncthreads();
    if (tid == 0) {
        float bb = wbest[0]; int bi = widx[0];
        for (int w = 1; w < 8; w++)
            if (wbest[w] < bb || (wbest[w] == bb && widx[w] < bi)) { bb = wbest[w]; bi = widx[w]; }
        wbest[0] = bb; widx[0] = bi;
    }
    __syncthreads();
    int idx = widx[0];
    float mind = wbest[0];

    float qv = cb[idx * 256 + tid];
    q[(b * 256 + tid) * 64 + hw] = qv;
    float diff = qv - zf[tid];
    red[tid] = diff * diff;
    __syncthreads();
    for (int o = 128; o > 0; o >>= 1) {
        if (tid < o) red[tid] += red[tid + o];
        __syncthreads();
    }
    if (tid == 0) {
        rowloss[row] = red[0];
        out_idx[row] = (float)idx;
        out_mind[row] = mind;
    }
}

__global__ void lossfin(const float* __restrict__ rowloss, float* __restrict__ out) {
    __shared__ float sh[256];
    float s = 0.f;
    for (int i = threadIdx.x; i < 1024; i += 256) s += rowloss[i];
    sh[threadIdx.x] = s; __syncthreads();
    for (int o = 128; o > 0; o >>= 1) {
        if (threadIdx.x < o) sh[threadIdx.x] += sh[threadIdx.x + o];
        __syncthreads();
    }
    if (threadIdx.x == 0) {
        float L = sh[0] / (1024.f * 256.f);
        out[786432] = L;
        out[786433] = L;
    }
}

// ---------------- final 1x1 conv + tanh -------------------------------------
__global__ void final1x1(const float* __restrict__ h, const float* __restrict__ w3,
                         const float* __restrict__ b3,
                         const float* __restrict__ scale, const float* __restrict__ shift,
                         float* __restrict__ out) {
    __shared__ float sw[96], ssc[32], ssh[32], sb[3];
    if (threadIdx.x < 96) sw[threadIdx.x] = w3[threadIdx.x];
    if (threadIdx.x < 32) { ssc[threadIdx.x] = scale[threadIdx.x];
                            ssh[threadIdx.x] = shift[threadIdx.x]; }
    if (threadIdx.x < 3) sb[threadIdx.x] = b3[threadIdx.x];
    __syncthreads();
    const int HW = 128 * 128;
    int gid = blockIdx.x * blockDim.x + threadIdx.x;
    int b = gid / HW, r = gid % HW;
    float a0 = 0.f, a1 = 0.f, a2 = 0.f;
#pragma unroll 8
    for (int c = 0; c < 32; c++) {
        float v = h[(b * 32 + c) * HW + r];
        v = v * ssc[c] + ssh[c];
        v = fmaxf(v, LEAKK * v);
        a0 += v * sw[c];
        a1 += v * sw[32 + c];
        a2 += v * sw[64 + c];
    }
    out[(b * 3 + 0) * HW + r] = tanhf(a0 + sb[0]);
    out[(b * 3 + 1) * HW + r] = tanhf(a1 + sb[1]);
    out[(b * 3 + 2) * HW + r] = tanhf(a2 + sb[2]);
}

// ----------------------------------------------------------------------------
extern "C" void kernel_launch(void* const* d_in, const int* in_sizes, int n_in,
                              void* d_out, int out_size) {
    (void)n_in; (void)out_size;

    const float* x = (const float*)d_in[0];
    const float *ew0, *eb0, *eg0, *ebb0;
    const float *ew1, *eg1, *ebb1;
    const float *ew2, *eg2, *ebb2;
    const float *ew3, *eb3;

    if (in_sizes[3] == 64) {
        ew0 = (const float*)d_in[1];  eb0 = (const float*)d_in[2];
        eg0 = (const float*)d_in[3];  ebb0 = (const float*)d_in[4];
        ew1 = (const float*)d_in[5];
        eg1 = (const float*)d_in[7];  ebb1 = (const float*)d_in[8];
        ew2 = (const float*)d_in[9];
        eg2 = (const float*)d_in[11]; ebb2 = (const float*)d_in[12];
        ew3 = (const float*)d_in[13]; eb3 = (const float*)d_in[14];
    } else {
        ew0 = (const float*)d_in[1];  eb0 = (const float*)d_in[2];
        ew1 = (const float*)d_in[3];
        ew2 = (const float*)d_in[5];
        ew3 = (const float*)d_in[7];  eb3 = (const float*)d_in[8];
        eg0 = (const float*)d_in[9];  ebb0 = (const float*)d_in[10];
        eg1 = (const float*)d_in[11]; ebb1 = (const float*)d_in[12];
        eg2 = (const float*)d_in[13]; ebb2 = (const float*)d_in[14];
    }

    const float* cb   = (const float*)d_in[15];
    const float* dw0  = (const float*)d_in[16];
    const float* dg0  = (const float*)d_in[18];
    const float* dbb0 = (const float*)d_in[19];
    const float* dw1  = (const float*)d_in[20];
    const float* dg1  = (const float*)d_in[22];
    const float* dbb1 = (const float*)d_in[23];
    const float* dw2  = (const float*)d_in[24];
    const float* dg2  = (const float*)d_in[26];
    const float* dbb2 = (const float*)d_in[27];
    const float* dw3  = (const float*)d_in[28];
    const float* db3  = (const float*)d_in[29];
    float* out = (float*)d_out;

    float *y0, *y1, *y2, *z, *q, *d0, *d1, *d2, *wt, *part, *sc, *sf, *cn, *rl;
    bf16 *wbh, *wbl;
    float2* bnp;
    cudaGetSymbolAddress((void**)&y0, g_y0);
    cudaGetSymbolAddress((void**)&y1, g_y1);
    cudaGetSymbolAddress((void**)&y2, g_y2);
    cudaGetSymbolAddress((void**)&z,  g_z);
    cudaGetSymbolAddress((void**)&q,  g_q);
    cudaGetSymbolAddress((void**)&d0, g_d0);
    cudaGetSymbolAddress((void**)&d1, g_d1);
    cudaGetSymbolAddress((void**)&d2, g_d2);
    cudaGetSymbolAddress((void**)&wt, g_wt);
    cudaGetSymbolAddress((void**)&part, g_part);
    cudaGetSymbolAddress((void**)&wbh, g_wbh);
    cudaGetSymbolAddress((void**)&wbl, g_wbl);
    cudaGetSymbolAddress((void**)&sc, g_scale);
    cudaGetSymbolAddress((void**)&sf, g_shift);
    cudaGetSymbolAddress((void**)&cn, g_cnorm);
    cudaGetSymbolAddress((void**)&rl, g_rowloss);
    cudaGetSymbolAddress((void**)&bnp, g_bnp);

    const long OF_E1 = 0, OF_E2 = 131072, OF_E3 = 655360;
    const long OF_D0 = 1703936, OF_D1 = 2228224, OF_D2 = 2260992;

    dim3 t32(32, 8);
    wtrans<<<dim3(2, 2), t32>>>(ew0, wt, 64, 48);
    wsplit<<<512,  256>>>(ew1, wbh + OF_E1, wbl + OF_E1, 131072);
    wsplit<<<2048, 256>>>(ew2, wbh + OF_E2, wbl + OF_E2, 524288);
    wsplit<<<4096, 256>>>(ew3, wbh + OF_E3, wbl + OF_E3, 1048576);
    wsplit_t<<<dim3(64, 8), t32>>>(dw0, wbh + OF_D0, wbl + OF_D0, 256, 2048);
    wsplit_t<<<dim3(8, 4),  t32>>>(dw1, wbh + OF_D1, wbl + OF_D1, 128, 256);
    wsplit_t<<<dim3(4, 2),  t32>>>(dw2, wbh + OF_D2, wbl + OF_D2, 64, 128);
    cnormk<<<512, 256>>>(cb, cn);

    // ---- encoder ----
    gconv<3, 64, 128, 128><<<dim3(1024, 1), 256>>>(x, wt, eb0, y0);
    bnpart<<<dim3(64, 8), 256>>>(y0, 64, 4096, bnp);
    bnfin<<<1, 64>>>(bnp, eg0, ebb0, sc + 0*256, sf + 0*256, 64, 1.f/(16.f*4096.f));

    tconv<64, 128, 64, 64, true, 2><<<dim3(128, 1, 2), 256>>>(y0, wbh + OF_E1, wbl + OF_E1, sc + 0*256, sf + 0*256, part);
    combine<<<8192, 256>>>(part, nullptr, y1, 2097152, 2, 1024, 128);
    bnpart<<<dim3(128, 8), 256>>>(y1, 128, 1024, bnp);
    bnfin<<<1, 128>>>(bnp, eg1, ebb1, sc + 1*256, sf + 1*256, 128, 1.f/(16.f*1024.f));

    tconv<128, 256, 32, 32, true, 4><<<dim3(32, 2, 4), 256>>>(y1, wbh + OF_E2, wbl + OF_E2, sc + 1*256, sf + 1*256, part);
    combine<<<4096, 256>>>(part, nullptr, y2, 1048576, 4, 256, 256);
    bnpart<<<dim3(256, 8), 256>>>(y2, 256, 256, bnp);
    bnfin<<<1, 256>>>(bnp, eg2, ebb2, sc + 2*256, sf + 2*256, 256, 1.f/(16.f*256.f));

    tconv<256, 256, 16, 16, true, 16><<<dim3(8, 2, 16), 256>>>(y2, wbh + OF_E3, wbl + OF_E3, sc + 2*256, sf + 2*256, part);
    combine<<<1024, 256>>>(part, eb3, z, 262144, 16, 64, 256);

    // ---- vector quantizer ----
    vqk<<<1024, 256>>>(z, cb, cn, q, rl, out + 786434, out + 786434 + 1024);
    lossfin<<<1, 256>>>(rl, out);

    // ---- decoder ----
    tconvt<256, 128, 4, 8, 8, false, 2><<<dim3(8, 16, 2), 256>>>(q, wbh + OF_D0, wbl + OF_D0, nullptr, nullptr, part);
    combine<<<8192, 256>>>(part, nullptr, d0, 2097152, 2, 1024, 128);
    bnpart<<<dim3(128, 8), 256>>>(d0, 128, 1024, bnp);
    bnfin<<<1, 128>>>(bnp, dg0, dbb0, sc + 3*256, sf + 3*256, 128, 1.f/(16.f*1024.f));

    tconvt<128, 64, 2, 32, 32, true, 1><<<dim3(128, 2, 1), 256>>>(d0, wbh + OF_D1, wbl + OF_D1, sc + 3*256, sf + 3*256, d1);
    bnpart<<<dim3(64, 8), 256>>>(d1, 64, 4096, bnp);
    bnfin<<<1, 64>>>(bnp, dg1, dbb1, sc + 4*256, sf + 4*256, 64, 1.f/(16.f*4096.f));

    tconvt<64, 32, 2, 64, 64, true, 1><<<dim3(512, 1, 1), 256>>>(d1, wbh + OF_D2, wbl + OF_D2, sc + 4*256, sf + 4*256, d2);
    bnpart<<<dim3(32, 8), 256>>>(d2, 32, 16384, bnp);
    bnfin<<<1, 32>>>(bnp, dg2, dbb2, sc + 5*256, sf + 5*256, 32, 1.f/(16.f*16384.f));

    final1x1<<<1024, 256>>>(d2, dw3, db3, sc + 5*256, sf + 5*256, out);
}